// round 2
// baseline (speedup 1.0000x reference)
#include <cuda_runtime.h>
#include <math.h>
#include <stdint.h>

// Problem constants
#define Bb 2
#define Tt 2048
#define Ee 1024
#define Hh 8
#define Dd 512
// Derived: B*T = 4096 rows, H*D = 4096 cols

// ---------------------------------------------------------------------------
// Scratch (device globals; no runtime allocation allowed)
// q,k,v,o stored as [B*T, H*D] row-major: element (b,t,h,d) at (b*T+t)*4096 + h*512 + d
// scores stored as [B*H, T, T]
// ---------------------------------------------------------------------------
__device__ float g_q[4096ull * 4096];
__device__ float g_k[4096ull * 4096];
__device__ float g_v[4096ull * 4096];
__device__ float g_o[4096ull * 4096];
__device__ float g_s[16ull * 2048 * 2048];

// ---------------------------------------------------------------------------
// Generic NT SGEMM: C[m,n] = sum_k A[m,k] * B[n,k]
// 128x128 block tile, BK=8, 256 threads, 8x8 per thread, register prefetch.
// Requires M,N multiples of 128, K multiple of 8.
// ---------------------------------------------------------------------------
__global__ __launch_bounds__(256, 2) void gemm_nt(
    const float* __restrict__ A, int lda,
    const float* __restrict__ Bm, int ldb,
    float* __restrict__ C, int ldc, int K)
{
    __shared__ float As[8][128];
    __shared__ float Bs[8][128];

    const int m0 = blockIdx.y * 128;
    const int n0 = blockIdx.x * 128;
    const int tid = threadIdx.x;
    const int tx = tid & 15;       // 0..15, N direction
    const int ty = tid >> 4;       // 0..15, M direction
    const int lrow = tid >> 1;     // 0..127
    const int lcol = (tid & 1) * 4;

    const float* Ap = A + (size_t)(m0 + lrow) * lda + lcol;
    const float* Bp = Bm + (size_t)(n0 + lrow) * ldb + lcol;

    float acc[8][8];
#pragma unroll
    for (int i = 0; i < 8; i++)
#pragma unroll
        for (int j = 0; j < 8; j++) acc[i][j] = 0.f;

    float4 na = *(const float4*)(Ap);
    float4 nb = *(const float4*)(Bp);

    for (int k0 = 0; k0 < K; k0 += 8) {
        As[lcol + 0][lrow] = na.x; As[lcol + 1][lrow] = na.y;
        As[lcol + 2][lrow] = na.z; As[lcol + 3][lrow] = na.w;
        Bs[lcol + 0][lrow] = nb.x; Bs[lcol + 1][lrow] = nb.y;
        Bs[lcol + 2][lrow] = nb.z; Bs[lcol + 3][lrow] = nb.w;
        __syncthreads();

        if (k0 + 8 < K) {
            na = *(const float4*)(Ap + k0 + 8);
            nb = *(const float4*)(Bp + k0 + 8);
        }

#pragma unroll
        for (int k = 0; k < 8; k++) {
            float af[8], bf[8];
            *(float4*)(af)     = *(const float4*)&As[k][ty * 8];
            *(float4*)(af + 4) = *(const float4*)&As[k][ty * 8 + 4];
            *(float4*)(bf)     = *(const float4*)&Bs[k][tx * 8];
            *(float4*)(bf + 4) = *(const float4*)&Bs[k][tx * 8 + 4];
#pragma unroll
            for (int i = 0; i < 8; i++)
#pragma unroll
                for (int j = 0; j < 8; j++)
                    acc[i][j] = fmaf(af[i], bf[j], acc[i][j]);
        }
        __syncthreads();
    }

#pragma unroll
    for (int i = 0; i < 8; i++) {
        float* Cr = C + (size_t)(m0 + ty * 8 + i) * ldc + n0 + tx * 8;
        *(float4*)(Cr)     = make_float4(acc[i][0], acc[i][1], acc[i][2], acc[i][3]);
        *(float4*)(Cr + 4) = make_float4(acc[i][4], acc[i][5], acc[i][6], acc[i][7]);
    }
}

// ---------------------------------------------------------------------------
// RoPE in-place on g_q and g_k. One thread per (even,odd) pair.
// Total pairs per buffer: 4096 rows * 2048 pairs = 8388608. Grid covers both.
// ---------------------------------------------------------------------------
__global__ __launch_bounds__(256) void rope_kernel()
{
    const size_t gid = (size_t)blockIdx.x * 256 + threadIdx.x; // 0 .. 16777215
    const size_t half = 8388608ull;
    float* buf = (gid >= half) ? g_k : g_q;
    const size_t id = gid & (half - 1);

    const int row = (int)(id >> 11);   // / 2048 pairs per row
    const int p   = (int)(id & 2047);
    const int h = p >> 8;              // / 256 pairs per head
    const int i = p & 255;             // freq index
    const int t = row & (Tt - 1);      // position within sequence

    // inv_freq = 1 / 10000^(2i/512), mirroring the reference fp32 computation
    const float expo = (float)(2 * i) * (1.0f / 512.0f);
    const float inv_f = 1.0f / powf(10000.0f, expo);
    const float ang = (float)t * inv_f;   // fp32, matches reference rounding
    float sn, cs;
    sincosf(ang, &sn, &cs);

    const size_t idx = (size_t)row * 4096 + h * 512 + 2 * i;
    const float x1 = buf[idx];
    const float x2 = buf[idx + 1];
    buf[idx]     = x1 * cs - x2 * sn;
    buf[idx + 1] = x1 * sn + x2 * cs;
}

// ---------------------------------------------------------------------------
// Scores: per (b,h): S[t,s] = scale * dot(q[t,:], k[s,:]); causal block skip.
// Grid (16,16,16): x = s-block, y = t-block, z = b*H+h. Upper blocks skipped.
// ---------------------------------------------------------------------------
__global__ __launch_bounds__(256, 2) void gemm_scores()
{
    if (blockIdx.x > blockIdx.y) return;   // strictly upper block: never needed

    const int z = blockIdx.z;
    const int b = z >> 3, h = z & 7;
    const size_t base = (size_t)b * Tt * 4096 + (size_t)h * 512;
    const float* A  = g_q + base;   // [T, 512], lda 4096
    const float* Bm = g_k + base;
    float* C = g_s + (size_t)z * Tt * Tt;  // ldc 2048
    const int lda = 4096, ldb = 4096, ldc = 2048, K = 512;

    __shared__ float As[8][128];
    __shared__ float Bs[8][128];
    const int m0 = blockIdx.y * 128;
    const int n0 = blockIdx.x * 128;
    const int tid = threadIdx.x;
    const int tx = tid & 15, ty = tid >> 4;
    const int lrow = tid >> 1;
    const int lcol = (tid & 1) * 4;

    const float* Ap = A + (size_t)(m0 + lrow) * lda + lcol;
    const float* Bp = Bm + (size_t)(n0 + lrow) * ldb + lcol;

    float acc[8][8];
#pragma unroll
    for (int i = 0; i < 8; i++)
#pragma unroll
        for (int j = 0; j < 8; j++) acc[i][j] = 0.f;

    float4 na = *(const float4*)(Ap);
    float4 nb = *(const float4*)(Bp);

    for (int k0 = 0; k0 < K; k0 += 8) {
        As[lcol + 0][lrow] = na.x; As[lcol + 1][lrow] = na.y;
        As[lcol + 2][lrow] = na.z; As[lcol + 3][lrow] = na.w;
        Bs[lcol + 0][lrow] = nb.x; Bs[lcol + 1][lrow] = nb.y;
        Bs[lcol + 2][lrow] = nb.z; Bs[lcol + 3][lrow] = nb.w;
        __syncthreads();
        if (k0 + 8 < K) {
            na = *(const float4*)(Ap + k0 + 8);
            nb = *(const float4*)(Bp + k0 + 8);
        }
#pragma unroll
        for (int k = 0; k < 8; k++) {
            float af[8], bf[8];
            *(float4*)(af)     = *(const float4*)&As[k][ty * 8];
            *(float4*)(af + 4) = *(const float4*)&As[k][ty * 8 + 4];
            *(float4*)(bf)     = *(const float4*)&Bs[k][tx * 8];
            *(float4*)(bf + 4) = *(const float4*)&Bs[k][tx * 8 + 4];
#pragma unroll
            for (int i = 0; i < 8; i++)
#pragma unroll
                for (int j = 0; j < 8; j++)
                    acc[i][j] = fmaf(af[i], bf[j], acc[i][j]);
        }
        __syncthreads();
    }

    const float scale = 0.044194173824159216f; // 1/sqrt(512)
#pragma unroll
    for (int i = 0; i < 8; i++) {
        const int tt = m0 + ty * 8 + i;
        float* Cr = C + (size_t)tt * ldc + n0 + tx * 8;
        float vals[8];
#pragma unroll
        for (int j = 0; j < 8; j++) {
            const int ss = n0 + tx * 8 + j;
            vals[j] = (ss > tt) ? -1e9f : acc[i][j] * scale;
        }
        *(float4*)(Cr)     = make_float4(vals[0], vals[1], vals[2], vals[3]);
        *(float4*)(Cr + 4) = make_float4(vals[4], vals[5], vals[6], vals[7]);
    }
}

// ---------------------------------------------------------------------------
// Row softmax over causal range [0, t]; zero-fills (t, T) so AV can run dense.
// One block (256 threads) per row. Grid = B*H*T = 32768.
// ---------------------------------------------------------------------------
__global__ __launch_bounds__(256) void softmax_kernel()
{
    const int r = blockIdx.x;          // z*T + t
    const int t = r & (Tt - 1);
    float* row = g_s + (size_t)r * Tt;
    const int len = t + 1;
    const int tid = threadIdx.x;
    __shared__ float red[256];

    float m = -1e30f;
    for (int s = tid; s < len; s += 256) m = fmaxf(m, row[s]);
    red[tid] = m;
    __syncthreads();
#pragma unroll
    for (int off = 128; off > 0; off >>= 1) {
        if (tid < off) red[tid] = fmaxf(red[tid], red[tid + off]);
        __syncthreads();
    }
    m = red[0];
    __syncthreads();

    float sum = 0.f;
    for (int s = tid; s < len; s += 256) {
        const float e = expf(row[s] - m);
        row[s] = e;
        sum += e;
    }
    red[tid] = sum;
    __syncthreads();
#pragma unroll
    for (int off = 128; off > 0; off >>= 1) {
        if (tid < off) red[tid] += red[tid + off];
        __syncthreads();
    }
    const float inv = 1.0f / red[0];

    for (int s = tid; s < len; s += 256) row[s] *= inv;
    for (int s = tid; s < Tt; s += 256)
        if (s >= len) row[s] = 0.f;
}

// ---------------------------------------------------------------------------
// AV: per (b,h): O[t,d] = sum_s P[t,s] * V[s,d]  (NN gemm)
// Grid (4,16,16): x = d-block (512/128), y = t-block, z = b*H+h.
// K limited to (y+1)*128 rows of keys (rest of P row is zero anyway).
// ---------------------------------------------------------------------------
__global__ __launch_bounds__(256, 2) void gemm_av()
{
    const int z = blockIdx.z;
    const int b = z >> 3, h = z & 7;
    const size_t vbase = (size_t)b * Tt * 4096 + (size_t)h * 512;
    const float* A  = g_s + (size_t)z * Tt * Tt;  // [T, T] probs, lda 2048
    const float* Bm = g_v + vbase;                // [T, 512], ldb 4096
    float* C = g_o + vbase;                       // ldc 4096
    const int lda = 2048, ldb = 4096, ldc = 4096;
    const int K = (blockIdx.y + 1) * 128;

    __shared__ float As[8][128];
    __shared__ float Bs[8][128];
    const int m0 = blockIdx.y * 128;
    const int n0 = blockIdx.x * 128;
    const int tid = threadIdx.x;
    const int tx = tid & 15, ty = tid >> 4;

    // A loads (row-major, K contiguous): same scheme as NT A operand
    const int alrow = tid >> 1;
    const int alcol = (tid & 1) * 4;
    const float* Ap = A + (size_t)(m0 + alrow) * lda + alcol;

    // B loads (row-major [K, N]): 8 rows x 128 cols per tile, no transpose
    const int brow = tid >> 5;           // 0..7
    const int bcol = (tid & 31) * 4;     // 0..124
    const float* Bp = Bm + (size_t)brow * ldb + n0 + bcol;

    float acc[8][8];
#pragma unroll
    for (int i = 0; i < 8; i++)
#pragma unroll
        for (int j = 0; j < 8; j++) acc[i][j] = 0.f;

    float4 na = *(const float4*)(Ap);
    float4 nb = *(const float4*)(Bp);

    for (int k0 = 0; k0 < K; k0 += 8) {
        As[alcol + 0][alrow] = na.x; As[alcol + 1][alrow] = na.y;
        As[alcol + 2][alrow] = na.z; As[alcol + 3][alrow] = na.w;
        *(float4*)&Bs[brow][bcol] = nb;
        __syncthreads();
        if (k0 + 8 < K) {
            na = *(const float4*)(Ap + k0 + 8);
            nb = *(const float4*)(Bp + (size_t)(k0 + 8) * ldb);
        }
#pragma unroll
        for (int k = 0; k < 8; k++) {
            float af[8], bf[8];
            *(float4*)(af)     = *(const float4*)&As[k][ty * 8];
            *(float4*)(af + 4) = *(const float4*)&As[k][ty * 8 + 4];
            *(float4*)(bf)     = *(const float4*)&Bs[k][tx * 8];
            *(float4*)(bf + 4) = *(const float4*)&Bs[k][tx * 8 + 4];
#pragma unroll
            for (int i = 0; i < 8; i++)
#pragma unroll
                for (int j = 0; j < 8; j++)
                    acc[i][j] = fmaf(af[i], bf[j], acc[i][j]);
        }
        __syncthreads();
    }

#pragma unroll
    for (int i = 0; i < 8; i++) {
        float* Cr = C + (size_t)(m0 + ty * 8 + i) * ldc + n0 + tx * 8;
        *(float4*)(Cr)     = make_float4(acc[i][0], acc[i][1], acc[i][2], acc[i][3]);
        *(float4*)(Cr + 4) = make_float4(acc[i][4], acc[i][5], acc[i][6], acc[i][7]);
    }
}

// ---------------------------------------------------------------------------
// Host orchestration
// ---------------------------------------------------------------------------
extern "C" void kernel_launch(void* const* d_in, const int* in_sizes, int n_in,
                              void* d_out, int out_size)
{
    const float* x  = (const float*)d_in[0];
    const float* wq = (const float*)d_in[1];
    const float* wk = (const float*)d_in[2];
    const float* wv = (const float*)d_in[3];
    const float* wo = (const float*)d_in[4];
    float* out = (float*)d_out;

    float *q, *k, *v, *o;
    cudaGetSymbolAddress((void**)&q, g_q);
    cudaGetSymbolAddress((void**)&k, g_k);
    cudaGetSymbolAddress((void**)&v, g_v);
    cudaGetSymbolAddress((void**)&o, g_o);

    // QKV projections: [4096,1024] @ [4096,1024]^T -> [4096,4096]
    gemm_nt<<<dim3(32, 32), 256>>>(x, Ee, wq, Ee, q, 4096, Ee);
    gemm_nt<<<dim3(32, 32), 256>>>(x, Ee, wk, Ee, k, 4096, Ee);
    gemm_nt<<<dim3(32, 32), 256>>>(x, Ee, wv, Ee, v, 4096, Ee);

    // RoPE on q and k (16777216 pairs total)
    rope_kernel<<<65536, 256>>>();

    // Causal scores (lower-triangular blocks only)
    gemm_scores<<<dim3(16, 16, 16), 256>>>();

    // Softmax per row
    softmax_kernel<<<32768, 256>>>();

    // attn @ V
    gemm_av<<<dim3(4, 16, 16), 256>>>();

    // Output projection: [4096,4096] @ [1024,4096]^T -> [4096,1024]
    gemm_nt<<<dim3(8, 32), 256>>>(o, 4096, wo, 4096, out, Ee, 4096);
}

// round 4
// speedup vs baseline: 1.9399x; 1.9399x over previous
#include <cuda_runtime.h>
#include <cuda_bf16.h>
#include <math.h>
#include <stdint.h>

// Problem: B=2, T=2048, E=1024, H=8, D=512.  B*T=4096 rows, H*D=4096.
#define TT 2048

// ---------------------------------------------------------------------------
// Device scratch
// ---------------------------------------------------------------------------
__device__ float g_q[4096ull * 4096];            // fp32 Q (pre-rope)
__device__ float g_k[4096ull * 4096];            // fp32 K (pre-rope)
__device__ float g_v[4096ull * 4096];            // fp32 V
__device__ float g_s[16ull * 2048 * 2048];       // fp32 scores

__device__ __nv_bfloat16 g_xh[4096ull * 1024], g_xl[4096ull * 1024];
__device__ __nv_bfloat16 g_wqh[4096ull * 1024], g_wql[4096ull * 1024];
__device__ __nv_bfloat16 g_wkh[4096ull * 1024], g_wkl[4096ull * 1024];
__device__ __nv_bfloat16 g_wvh[4096ull * 1024], g_wvl[4096ull * 1024];
__device__ __nv_bfloat16 g_woh[1024ull * 4096], g_wol[1024ull * 4096];
__device__ __nv_bfloat16 g_qh[4096ull * 4096], g_ql[4096ull * 4096];
__device__ __nv_bfloat16 g_kh[4096ull * 4096], g_kl[4096ull * 4096];
__device__ __nv_bfloat16 g_vth[16ull * 512 * 2048], g_vtl[16ull * 512 * 2048];
__device__ __nv_bfloat16 g_ph[16ull * 2048 * 2048], g_pl[16ull * 2048 * 2048];
__device__ __nv_bfloat16 g_oh[4096ull * 4096], g_ol[4096ull * 4096];

// ---------------------------------------------------------------------------
// PTX helpers (arch-portable: cp.async / ldmatrix / mma.sync, all sm_80+)
// ---------------------------------------------------------------------------
__device__ __forceinline__ uint32_t s2u(const void* p) {
    uint32_t a;
    asm("{ .reg .u64 t; cvta.to.shared.u64 t, %1; cvt.u32.u64 %0, t; }" : "=r"(a) : "l"(p));
    return a;
}
__device__ __forceinline__ void cpa16(uint32_t dst, const void* src) {
    asm volatile("cp.async.cg.shared.global [%0], [%1], 16;" :: "r"(dst), "l"(src));
}
#define CP_COMMIT() asm volatile("cp.async.commit_group;" ::: "memory")
#define CP_WAIT(n)  asm volatile("cp.async.wait_group %0;" :: "n"(n) : "memory")

__device__ __forceinline__ void ldsm4(uint32_t* r, uint32_t addr) {
    asm volatile("ldmatrix.sync.aligned.m8n8.x4.shared.b16 {%0,%1,%2,%3}, [%4];"
                 : "=r"(r[0]), "=r"(r[1]), "=r"(r[2]), "=r"(r[3]) : "r"(addr));
}
__device__ __forceinline__ void mma16816(float* d, const uint32_t* a, const uint32_t* b) {
    asm volatile(
        "mma.sync.aligned.m16n8k16.row.col.f32.bf16.bf16.f32 "
        "{%0,%1,%2,%3}, {%4,%5,%6,%7}, {%8,%9}, {%0,%1,%2,%3};"
        : "+f"(d[0]), "+f"(d[1]), "+f"(d[2]), "+f"(d[3])
        : "r"(a[0]), "r"(a[1]), "r"(a[2]), "r"(a[3]), "r"(b[0]), "r"(b[1]));
}

// ---------------------------------------------------------------------------
// GEMM core: C[128,128] += (Ah+Al)[128,K] * (Bh+Bl)[128,K]^T, 3-combo split.
// BK=32, 2-stage cp.async double buffer.
// smem stage layout: Ah @0, Al @10240, Bh @20480, Bl @30720 ; rows of 40 bf16
// (80B, +16B pad) -> ldmatrix conflict-free. Stage size 40960B, 2 stages.
// ---------------------------------------------------------------------------
#define STAGE_BYTES 40960
#define SMEM_BYTES  (2 * STAGE_BYTES)

__device__ __forceinline__ void stage_load(
    const __nv_bfloat16* __restrict__ ah, const __nv_bfloat16* __restrict__ al, int lda,
    const __nv_bfloat16* __restrict__ bh, const __nv_bfloat16* __restrict__ bl, int ldb,
    int k0, uint32_t sdst)
{
    const int tid = threadIdx.x;
#pragma unroll
    for (int i = 0; i < 8; i++) {
        const int c = tid + i * 256;       // 0..2047
        const int mat = c >> 9;            // 0..3 (constant per i-pair)
        const int r = (c >> 2) & 127;
        const int c16 = c & 3;
        const __nv_bfloat16* src;
        int ld;
        if (mat == 0)      { src = ah; ld = lda; }
        else if (mat == 1) { src = al; ld = lda; }
        else if (mat == 2) { src = bh; ld = ldb; }
        else               { src = bl; ld = ldb; }
        src += (size_t)r * ld + k0 + c16 * 8;
        cpa16(sdst + mat * 10240 + r * 80 + c16 * 16, src);
    }
}

__device__ __forceinline__ void stage_compute(uint32_t sb, float acc[2][8][4]) {
    const int lane = threadIdx.x & 31;
    const int wid = threadIdx.x >> 5;
    const int wm = (wid & 3) * 32;
    const int wn = (wid >> 2) * 64;
    const int lrow = lane & 15;
    const int lkof = (lane >> 4) * 16;   // byte offset of 8-bf16 half
#pragma unroll
    for (int kk = 0; kk < 2; kk++) {
        uint32_t Ah[2][4], Al[2][4], Bh[8][2], Bl[8][2];
#pragma unroll
        for (int mi = 0; mi < 2; mi++) {
            const uint32_t ad = sb + (wm + mi * 16 + lrow) * 80 + kk * 32 + lkof;
            ldsm4(Ah[mi], ad);
            ldsm4(Al[mi], ad + 10240);
        }
#pragma unroll
        for (int jj = 0; jj < 4; jj++) {
            const uint32_t bd = sb + 20480 + (wn + jj * 16 + lrow) * 80 + kk * 32 + lkof;
            uint32_t t[4];
            ldsm4(t, bd);
            Bh[2 * jj][0] = t[0]; Bh[2 * jj][1] = t[2];
            Bh[2 * jj + 1][0] = t[1]; Bh[2 * jj + 1][1] = t[3];
            ldsm4(t, bd + 10240);
            Bl[2 * jj][0] = t[0]; Bl[2 * jj][1] = t[2];
            Bl[2 * jj + 1][0] = t[1]; Bl[2 * jj + 1][1] = t[3];
        }
#pragma unroll
        for (int mi = 0; mi < 2; mi++)
#pragma unroll
            for (int j = 0; j < 8; j++) {
                mma16816(acc[mi][j], Ah[mi], Bh[j]);
                mma16816(acc[mi][j], Ah[mi], Bl[j]);
                mma16816(acc[mi][j], Al[mi], Bh[j]);
            }
    }
}

__device__ __forceinline__ void gemm_core(
    const __nv_bfloat16* ah, const __nv_bfloat16* al, int lda,
    const __nv_bfloat16* bh, const __nv_bfloat16* bl, int ldb,
    int nc, char* smem, float acc[2][8][4])
{
    const uint32_t sb = s2u(smem);
#pragma unroll
    for (int mi = 0; mi < 2; mi++)
#pragma unroll
        for (int j = 0; j < 8; j++)
#pragma unroll
            for (int q = 0; q < 4; q++) acc[mi][j][q] = 0.f;

    stage_load(ah, al, lda, bh, bl, ldb, 0, sb);
    CP_COMMIT();
    for (int c = 0; c < nc; c++) {
        if (c + 1 < nc) {
            stage_load(ah, al, lda, bh, bl, ldb, (c + 1) * 32, sb + ((c + 1) & 1) * STAGE_BYTES);
            CP_COMMIT();
            CP_WAIT(1);
        } else {
            CP_WAIT(0);
        }
        __syncthreads();
        stage_compute(sb + (c & 1) * STAGE_BYTES, acc);
        __syncthreads();
    }
}

// Epilogue index helpers (per warp/lane)
#define EPI_IDX()                                   \
    const int lane = threadIdx.x & 31;              \
    const int wid = threadIdx.x >> 5;               \
    const int wm = (wid & 3) * 32;                  \
    const int wn = (wid >> 2) * 64;                 \
    const int er = lane >> 2;                       \
    const int ec = (lane & 3) * 2;

// ---------------------------------------------------------------------------
// GEMM kernels
// ---------------------------------------------------------------------------
__global__ __launch_bounds__(256, 1) void gemm_qkv() {
    extern __shared__ char smem[];
    const int m0 = blockIdx.y * 128, n0 = blockIdx.x * 128;
    const int z = blockIdx.z;
    const __nv_bfloat16* bh = (z == 0) ? g_wqh : (z == 1) ? g_wkh : g_wvh;
    const __nv_bfloat16* bl = (z == 0) ? g_wql : (z == 1) ? g_wkl : g_wvl;
    float* C = (z == 0) ? g_q : (z == 1) ? g_k : g_v;

    float acc[2][8][4];
    gemm_core(g_xh + (size_t)m0 * 1024, g_xl + (size_t)m0 * 1024, 1024,
              bh + (size_t)n0 * 1024, bl + (size_t)n0 * 1024, 1024,
              32, smem, acc);
    EPI_IDX();
#pragma unroll
    for (int mi = 0; mi < 2; mi++)
#pragma unroll
        for (int j = 0; j < 8; j++) {
            const int rr = m0 + wm + mi * 16 + er;
            const int cc = n0 + wn + j * 8 + ec;
            *(float2*)&C[(size_t)rr * 4096 + cc] = make_float2(acc[mi][j][0], acc[mi][j][1]);
            *(float2*)&C[(size_t)(rr + 8) * 4096 + cc] = make_float2(acc[mi][j][2], acc[mi][j][3]);
        }
}

__global__ __launch_bounds__(256, 1) void gemm_scores() {
    if (blockIdx.x > blockIdx.y) return;
    extern __shared__ char smem[];
    const int z = blockIdx.z, b = z >> 3, h = z & 7;
    const size_t base = (size_t)b * TT * 4096 + (size_t)h * 512;
    const int m0 = blockIdx.y * 128, n0 = blockIdx.x * 128;

    float acc[2][8][4];
    gemm_core(g_qh + base + (size_t)m0 * 4096, g_ql + base + (size_t)m0 * 4096, 4096,
              g_kh + base + (size_t)n0 * 4096, g_kl + base + (size_t)n0 * 4096, 4096,
              16, smem, acc);
    EPI_IDX();
    const float scale = 0.044194173824159216f;  // 1/sqrt(512)
    float* C = g_s + (size_t)z * TT * TT;
#pragma unroll
    for (int mi = 0; mi < 2; mi++)
#pragma unroll
        for (int j = 0; j < 8; j++) {
            const int cc = n0 + wn + j * 8 + ec;
#pragma unroll
            for (int half = 0; half < 2; half++) {
                const int rr = m0 + wm + mi * 16 + er + half * 8;
                float v0 = (cc > rr) ? -1e9f : acc[mi][j][2 * half] * scale;
                float v1 = (cc + 1 > rr) ? -1e9f : acc[mi][j][2 * half + 1] * scale;
                *(float2*)&C[(size_t)rr * 2048 + cc] = make_float2(v0, v1);
            }
        }
}

__global__ __launch_bounds__(256, 1) void gemm_av() {
    extern __shared__ char smem[];
    const int z = blockIdx.z, b = z >> 3, h = z & 7;
    const int m0 = blockIdx.y * 128;       // t block
    const int d0 = blockIdx.x * 128;       // d block
    const int nc = (blockIdx.y + 1) * 4;   // causal K limit (chunks of 32)
    const size_t pbase = (size_t)z * TT * TT + (size_t)m0 * 2048;
    const size_t vbase = ((size_t)z * 512 + d0) * 2048;

    float acc[2][8][4];
    gemm_core(g_ph + pbase, g_pl + pbase, 2048,
              g_vth + vbase, g_vtl + vbase, 2048,
              nc, smem, acc);
    EPI_IDX();
#pragma unroll
    for (int mi = 0; mi < 2; mi++)
#pragma unroll
        for (int j = 0; j < 8; j++) {
            const int cc = d0 + wn + j * 8 + ec;
#pragma unroll
            for (int half = 0; half < 2; half++) {
                const int rr = m0 + wm + mi * 16 + er + half * 8;
                const size_t o = (size_t)(b * TT + rr) * 4096 + h * 512 + cc;
                const float v0 = acc[mi][j][2 * half], v1 = acc[mi][j][2 * half + 1];
                const __nv_bfloat16 h0 = __float2bfloat16(v0);
                const __nv_bfloat16 h1 = __float2bfloat16(v1);
                const __nv_bfloat16 l0 = __float2bfloat16(v0 - __bfloat162float(h0));
                const __nv_bfloat16 l1 = __float2bfloat16(v1 - __bfloat162float(h1));
                *(__nv_bfloat162*)&g_oh[o] = __nv_bfloat162(h0, h1);
                *(__nv_bfloat162*)&g_ol[o] = __nv_bfloat162(l0, l1);
            }
        }
}

__global__ __launch_bounds__(256, 1) void gemm_oproj(float* __restrict__ out) {
    extern __shared__ char smem[];
    const int m0 = blockIdx.y * 128, n0 = blockIdx.x * 128;
    float acc[2][8][4];
    gemm_core(g_oh + (size_t)m0 * 4096, g_ol + (size_t)m0 * 4096, 4096,
              g_woh + (size_t)n0 * 4096, g_wol + (size_t)n0 * 4096, 4096,
              128, smem, acc);
    EPI_IDX();
#pragma unroll
    for (int mi = 0; mi < 2; mi++)
#pragma unroll
        for (int j = 0; j < 8; j++) {
            const int rr = m0 + wm + mi * 16 + er;
            const int cc = n0 + wn + j * 8 + ec;
            *(float2*)&out[(size_t)rr * 1024 + cc] = make_float2(acc[mi][j][0], acc[mi][j][1]);
            *(float2*)&out[(size_t)(rr + 8) * 1024 + cc] = make_float2(acc[mi][j][2], acc[mi][j][3]);
        }
}

// ---------------------------------------------------------------------------
// fp32 -> bf16 hi/lo split, elementwise (4 per thread)
// ---------------------------------------------------------------------------
__global__ __launch_bounds__(256) void conv_split(const float* __restrict__ s,
                                                  __nv_bfloat16* __restrict__ h,
                                                  __nv_bfloat16* __restrict__ l, int n) {
    const int i = (blockIdx.x * 256 + threadIdx.x) * 4;
    if (i >= n) return;
    float4 v = *(const float4*)(s + i);
    float f[4] = {v.x, v.y, v.z, v.w};
    __nv_bfloat16 hh[4], ll[4];
#pragma unroll
    for (int q = 0; q < 4; q++) {
        hh[q] = __float2bfloat16(f[q]);
        ll[q] = __float2bfloat16(f[q] - __bfloat162float(hh[q]));
    }
    *(__nv_bfloat162*)(h + i)     = __nv_bfloat162(hh[0], hh[1]);
    *(__nv_bfloat162*)(h + i + 2) = __nv_bfloat162(hh[2], hh[3]);
    *(__nv_bfloat162*)(l + i)     = __nv_bfloat162(ll[0], ll[1]);
    *(__nv_bfloat162*)(l + i + 2) = __nv_bfloat162(ll[2], ll[3]);
}

// ---------------------------------------------------------------------------
// RoPE + split:  reads g_q/g_k fp32, writes qh/ql/kh/kl bf16.
// ---------------------------------------------------------------------------
__global__ __launch_bounds__(256) void rope_conv() {
    const size_t gid = (size_t)blockIdx.x * 256 + threadIdx.x;
    const size_t half = 8388608ull;
    const bool isK = gid >= half;
    const size_t id = gid & (half - 1);
    const int row = (int)(id >> 11);
    const int p = (int)(id & 2047);
    const int h = p >> 8;
    const int i = p & 255;
    const int t = row & (TT - 1);

    const float expo = (float)(2 * i) * (1.0f / 512.0f);
    const float inv_f = 1.0f / powf(10000.0f, expo);
    const float ang = (float)t * inv_f;
    float sn, cs;
    sincosf(ang, &sn, &cs);

    const size_t idx = (size_t)row * 4096 + h * 512 + 2 * i;
    const float* src = isK ? g_k : g_q;
    __nv_bfloat16* dh = isK ? g_kh : g_qh;
    __nv_bfloat16* dl = isK ? g_kl : g_ql;
    const float x1 = src[idx], x2 = src[idx + 1];
    const float r1 = x1 * cs - x2 * sn;
    const float r2 = x1 * sn + x2 * cs;
    __nv_bfloat16 h1 = __float2bfloat16(r1), h2 = __float2bfloat16(r2);
    __nv_bfloat16 l1 = __float2bfloat16(r1 - __bfloat162float(h1));
    __nv_bfloat16 l2 = __float2bfloat16(r2 - __bfloat162float(h2));
    *(__nv_bfloat162*)(dh + idx) = __nv_bfloat162(h1, h2);
    *(__nv_bfloat162*)(dl + idx) = __nv_bfloat162(l1, l2);
}

// ---------------------------------------------------------------------------
// V transpose + split: g_v[(b,t),(h,d)] -> vt[(b,h), d, s] bf16 hi/lo
// ---------------------------------------------------------------------------
__global__ __launch_bounds__(256) void v_trans() {
    __shared__ float tile[32][33];
    const int z = blockIdx.z, b = z >> 3, h = z & 7;
    const int s0 = blockIdx.x * 32, d0 = blockIdx.y * 32;
    const int tx = threadIdx.x, ty = threadIdx.y;
#pragma unroll
    for (int i = 0; i < 4; i++) {
        const int s = s0 + ty + i * 8;
        tile[ty + i * 8][tx] = g_v[(size_t)(b * TT + s) * 4096 + h * 512 + d0 + tx];
    }
    __syncthreads();
#pragma unroll
    for (int i = 0; i < 4; i++) {
        const int d = d0 + ty + i * 8;
        const float f = tile[tx][ty + i * 8];
        __nv_bfloat16 hi = __float2bfloat16(f);
        __nv_bfloat16 lo = __float2bfloat16(f - __bfloat162float(hi));
        const size_t o = ((size_t)z * 512 + d) * 2048 + s0 + tx;
        g_vth[o] = hi;
        g_vtl[o] = lo;
    }
}

// ---------------------------------------------------------------------------
// Softmax: fp32 scores in, bf16 hi/lo probs out (zero-filled upper).
// ---------------------------------------------------------------------------
__global__ __launch_bounds__(256) void softmax2() {
    const int rI = blockIdx.x;
    const int t = rI & (TT - 1);
    float* row = g_s + (size_t)rI * TT;
    __nv_bfloat16* ph = g_ph + (size_t)rI * TT;
    __nv_bfloat16* pl = g_pl + (size_t)rI * TT;
    const int len = t + 1;
    const int tid = threadIdx.x;
    __shared__ float red[256];

    float m = -1e30f;
    for (int s = tid; s < len; s += 256) m = fmaxf(m, row[s]);
    red[tid] = m;
    __syncthreads();
#pragma unroll
    for (int off = 128; off > 0; off >>= 1) {
        if (tid < off) red[tid] = fmaxf(red[tid], red[tid + off]);
        __syncthreads();
    }
    m = red[0];
    __syncthreads();

    float sum = 0.f;
    for (int s = tid; s < len; s += 256) {
        const float e = expf(row[s] - m);
        row[s] = e;
        sum += e;
    }
    red[tid] = sum;
    __syncthreads();
#pragma unroll
    for (int off = 128; off > 0; off >>= 1) {
        if (tid < off) red[tid] += red[tid + off];
        __syncthreads();
    }
    const float inv = 1.0f / red[0];

    for (int s = tid; s < len; s += 256) {
        const float pv = row[s] * inv;
        __nv_bfloat16 hi = __float2bfloat16(pv);
        ph[s] = hi;
        pl[s] = __float2bfloat16(pv - __bfloat162float(hi));
    }
    const __nv_bfloat16 z0 = __float2bfloat16(0.f);
    for (int s = len + tid; s < TT; s += 256) { ph[s] = z0; pl[s] = z0; }
}

// ---------------------------------------------------------------------------
// Host orchestration
// ---------------------------------------------------------------------------
extern "C" void kernel_launch(void* const* d_in, const int* in_sizes, int n_in,
                              void* d_out, int out_size)
{
    const float* x  = (const float*)d_in[0];
    const float* wq = (const float*)d_in[1];
    const float* wk = (const float*)d_in[2];
    const float* wv = (const float*)d_in[3];
    const float* wo = (const float*)d_in[4];
    float* out = (float*)d_out;

    cudaFuncSetAttribute(gemm_qkv,    cudaFuncAttributeMaxDynamicSharedMemorySize, SMEM_BYTES);
    cudaFuncSetAttribute(gemm_scores, cudaFuncAttributeMaxDynamicSharedMemorySize, SMEM_BYTES);
    cudaFuncSetAttribute(gemm_av,     cudaFuncAttributeMaxDynamicSharedMemorySize, SMEM_BYTES);
    cudaFuncSetAttribute(gemm_oproj,  cudaFuncAttributeMaxDynamicSharedMemorySize, SMEM_BYTES);

    __nv_bfloat16 *xh, *xl, *wqh, *wql, *wkh, *wkl, *wvh, *wvl, *woh, *wol;
    cudaGetSymbolAddress((void**)&xh, g_xh);   cudaGetSymbolAddress((void**)&xl, g_xl);
    cudaGetSymbolAddress((void**)&wqh, g_wqh); cudaGetSymbolAddress((void**)&wql, g_wql);
    cudaGetSymbolAddress((void**)&wkh, g_wkh); cudaGetSymbolAddress((void**)&wkl, g_wkl);
    cudaGetSymbolAddress((void**)&wvh, g_wvh); cudaGetSymbolAddress((void**)&wvl, g_wvl);
    cudaGetSymbolAddress((void**)&woh, g_woh); cudaGetSymbolAddress((void**)&wol, g_wol);

    const int n4m = 4096 * 1024;
    conv_split<<<n4m / 1024, 256>>>(x,  xh,  xl,  n4m);
    conv_split<<<n4m / 1024, 256>>>(wq, wqh, wql, n4m);
    conv_split<<<n4m / 1024, 256>>>(wk, wkh, wkl, n4m);
    conv_split<<<n4m / 1024, 256>>>(wv, wvh, wvl, n4m);
    conv_split<<<n4m / 1024, 256>>>(wo, woh, wol, n4m);

    gemm_qkv<<<dim3(32, 32, 3), 256, SMEM_BYTES>>>();
    rope_conv<<<65536, 256>>>();
    v_trans<<<dim3(64, 16, 16), dim3(32, 8)>>>();
    gemm_scores<<<dim3(16, 16, 16), 256, SMEM_BYTES>>>();
    softmax2<<<32768, 256>>>();
    gemm_av<<<dim3(4, 16, 16), 256, SMEM_BYTES>>>();
    gemm_oproj<<<dim3(8, 32), 256, SMEM_BYTES>>>(out);
}

// round 5
// speedup vs baseline: 2.0472x; 1.0553x over previous
#include <cuda_runtime.h>
#include <cuda_bf16.h>
#include <math.h>
#include <stdint.h>

// Problem: B=2, T=2048, E=1024, H=8, D=512.  B*T=4096 rows, H*D=4096.
#define TT 2048

// ---------------------------------------------------------------------------
// Device scratch
// ---------------------------------------------------------------------------
__device__ float g_q[4096ull * 4096];            // fp32 Q (pre-rope)
__device__ float g_k[4096ull * 4096];            // fp32 K (pre-rope)
__device__ float g_v[4096ull * 4096];            // fp32 V
__device__ float g_s[16ull * 2048 * 2048];       // fp32 scores

__device__ __nv_bfloat16 g_xh[4096ull * 1024], g_xl[4096ull * 1024];
__device__ __nv_bfloat16 g_wqh[4096ull * 1024], g_wql[4096ull * 1024];
__device__ __nv_bfloat16 g_wkh[4096ull * 1024], g_wkl[4096ull * 1024];
__device__ __nv_bfloat16 g_wvh[4096ull * 1024], g_wvl[4096ull * 1024];
__device__ __nv_bfloat16 g_woh[1024ull * 4096], g_wol[1024ull * 4096];
__device__ __nv_bfloat16 g_qh[4096ull * 4096], g_ql[4096ull * 4096];
__device__ __nv_bfloat16 g_kh[4096ull * 4096], g_kl[4096ull * 4096];
__device__ __nv_bfloat16 g_vth[16ull * 512 * 2048], g_vtl[16ull * 512 * 2048];
__device__ __nv_bfloat16 g_ph[16ull * 2048 * 2048], g_pl[16ull * 2048 * 2048];
__device__ __nv_bfloat16 g_oh[4096ull * 4096], g_ol[4096ull * 4096];

// ---------------------------------------------------------------------------
// PTX helpers (arch-portable: cp.async / ldmatrix / mma.sync, all sm_80+)
// ---------------------------------------------------------------------------
__device__ __forceinline__ uint32_t s2u(const void* p) {
    uint32_t a;
    asm("{ .reg .u64 t; cvta.to.shared.u64 t, %1; cvt.u32.u64 %0, t; }" : "=r"(a) : "l"(p));
    return a;
}
__device__ __forceinline__ void cpa16(uint32_t dst, const void* src) {
    asm volatile("cp.async.cg.shared.global [%0], [%1], 16;" :: "r"(dst), "l"(src));
}
#define CP_COMMIT() asm volatile("cp.async.commit_group;" ::: "memory")
#define CP_WAIT(n)  asm volatile("cp.async.wait_group %0;" :: "n"(n) : "memory")

__device__ __forceinline__ void ldsm4(uint32_t* r, uint32_t addr) {
    asm volatile("ldmatrix.sync.aligned.m8n8.x4.shared.b16 {%0,%1,%2,%3}, [%4];"
                 : "=r"(r[0]), "=r"(r[1]), "=r"(r[2]), "=r"(r[3]) : "r"(addr));
}
__device__ __forceinline__ void mma16816(float* d, const uint32_t* a, const uint32_t* b) {
    asm volatile(
        "mma.sync.aligned.m16n8k16.row.col.f32.bf16.bf16.f32 "
        "{%0,%1,%2,%3}, {%4,%5,%6,%7}, {%8,%9}, {%0,%1,%2,%3};"
        : "+f"(d[0]), "+f"(d[1]), "+f"(d[2]), "+f"(d[3])
        : "r"(a[0]), "r"(a[1]), "r"(a[2]), "r"(a[3]), "r"(b[0]), "r"(b[1]));
}

// ---------------------------------------------------------------------------
// GEMM core: C[128,128] += (Ah+Al)[128,K] * (Bh+Bl)[128,K]^T, 3-combo split.
// BK=32, 4-stage cp.async ring, ONE __syncthreads per chunk.
// smem stage layout: Ah @0, Al @10240, Bh @20480, Bl @30720 ; rows of 40 bf16
// (80B, +16B pad) -> ldmatrix conflict-free. Stage 40960B x 4 stages = 160KB.
// ---------------------------------------------------------------------------
#define STAGE_BYTES 40960
#define NSTAGE 4
#define SMEM_BYTES (NSTAGE * STAGE_BYTES)

__device__ __forceinline__ void stage_load(
    const __nv_bfloat16* __restrict__ ah, const __nv_bfloat16* __restrict__ al, int lda,
    const __nv_bfloat16* __restrict__ bh, const __nv_bfloat16* __restrict__ bl, int ldb,
    int k0, uint32_t sdst)
{
    const int tid = threadIdx.x;
#pragma unroll
    for (int i = 0; i < 8; i++) {
        const int c = tid + i * 256;       // 0..2047
        const int mat = c >> 9;            // 0..3
        const int r = (c >> 2) & 127;
        const int c16 = c & 3;
        const __nv_bfloat16* src;
        int ld;
        if (mat == 0)      { src = ah; ld = lda; }
        else if (mat == 1) { src = al; ld = lda; }
        else if (mat == 2) { src = bh; ld = ldb; }
        else               { src = bl; ld = ldb; }
        src += (size_t)r * ld + k0 + c16 * 8;
        cpa16(sdst + mat * 10240 + r * 80 + c16 * 16, src);
    }
}

__device__ __forceinline__ void stage_compute(uint32_t sb, float acc[2][8][4]) {
    const int lane = threadIdx.x & 31;
    const int wid = threadIdx.x >> 5;
    const int wm = (wid & 3) * 32;
    const int wn = (wid >> 2) * 64;
    const int lrow = lane & 15;
    const int lkof = (lane >> 4) * 16;   // byte offset of 8-bf16 half
#pragma unroll
    for (int kk = 0; kk < 2; kk++) {
        uint32_t Ah[2][4], Al[2][4], Bh[8][2], Bl[8][2];
#pragma unroll
        for (int mi = 0; mi < 2; mi++) {
            const uint32_t ad = sb + (wm + mi * 16 + lrow) * 80 + kk * 32 + lkof;
            ldsm4(Ah[mi], ad);
            ldsm4(Al[mi], ad + 10240);
        }
#pragma unroll
        for (int jj = 0; jj < 4; jj++) {
            const uint32_t bd = sb + 20480 + (wn + jj * 16 + lrow) * 80 + kk * 32 + lkof;
            uint32_t t[4];
            ldsm4(t, bd);
            Bh[2 * jj][0] = t[0]; Bh[2 * jj][1] = t[2];
            Bh[2 * jj + 1][0] = t[1]; Bh[2 * jj + 1][1] = t[3];
            ldsm4(t, bd + 10240);
            Bl[2 * jj][0] = t[0]; Bl[2 * jj][1] = t[2];
            Bl[2 * jj + 1][0] = t[1]; Bl[2 * jj + 1][1] = t[3];
        }
#pragma unroll
        for (int mi = 0; mi < 2; mi++)
#pragma unroll
            for (int j = 0; j < 8; j++) {
                mma16816(acc[mi][j], Ah[mi], Bh[j]);
                mma16816(acc[mi][j], Ah[mi], Bl[j]);
                mma16816(acc[mi][j], Al[mi], Bh[j]);
            }
    }
}

// nc must be >= 3 (all call sites have nc >= 4).
__device__ __forceinline__ void gemm_core(
    const __nv_bfloat16* ah, const __nv_bfloat16* al, int lda,
    const __nv_bfloat16* bh, const __nv_bfloat16* bl, int ldb,
    int nc, char* smem, float acc[2][8][4])
{
    const uint32_t sb = s2u(smem);
#pragma unroll
    for (int mi = 0; mi < 2; mi++)
#pragma unroll
        for (int j = 0; j < 8; j++)
#pragma unroll
            for (int q = 0; q < 4; q++) acc[mi][j][q] = 0.f;

#pragma unroll
    for (int s = 0; s < 3; s++) {
        stage_load(ah, al, lda, bh, bl, ldb, s * 32, sb + s * STAGE_BYTES);
        CP_COMMIT();
    }
    for (int c = 0; c < nc; c++) {
        // Guarantee stage c is complete before the barrier.
        if (c <= nc - 3)      { CP_WAIT(2); }
        else if (c == nc - 2) { CP_WAIT(1); }
        else                  { CP_WAIT(0); }
        __syncthreads();
        stage_compute(sb + (c & (NSTAGE - 1)) * STAGE_BYTES, acc);
        // Prefetch stage c+3 into buffer (c-1)&3, which all warps finished
        // reading before this iteration's barrier. No second barrier needed.
        if (c + 3 < nc) {
            stage_load(ah, al, lda, bh, bl, ldb, (c + 3) * 32,
                       sb + ((c + 3) & (NSTAGE - 1)) * STAGE_BYTES);
            CP_COMMIT();
        }
    }
}

// Epilogue index helpers (per warp/lane)
#define EPI_IDX()                                   \
    const int lane = threadIdx.x & 31;              \
    const int wid = threadIdx.x >> 5;               \
    const int wm = (wid & 3) * 32;                  \
    const int wn = (wid >> 2) * 64;                 \
    const int er = lane >> 2;                       \
    const int ec = (lane & 3) * 2;

// ---------------------------------------------------------------------------
// GEMM kernels
// ---------------------------------------------------------------------------
__global__ __launch_bounds__(256, 1) void gemm_qkv() {
    extern __shared__ char smem[];
    const int m0 = blockIdx.y * 128, n0 = blockIdx.x * 128;
    const int z = blockIdx.z;
    const __nv_bfloat16* bh = (z == 0) ? g_wqh : (z == 1) ? g_wkh : g_wvh;
    const __nv_bfloat16* bl = (z == 0) ? g_wql : (z == 1) ? g_wkl : g_wvl;
    float* C = (z == 0) ? g_q : (z == 1) ? g_k : g_v;

    float acc[2][8][4];
    gemm_core(g_xh + (size_t)m0 * 1024, g_xl + (size_t)m0 * 1024, 1024,
              bh + (size_t)n0 * 1024, bl + (size_t)n0 * 1024, 1024,
              32, smem, acc);
    EPI_IDX();
#pragma unroll
    for (int mi = 0; mi < 2; mi++)
#pragma unroll
        for (int j = 0; j < 8; j++) {
            const int rr = m0 + wm + mi * 16 + er;
            const int cc = n0 + wn + j * 8 + ec;
            *(float2*)&C[(size_t)rr * 4096 + cc] = make_float2(acc[mi][j][0], acc[mi][j][1]);
            *(float2*)&C[(size_t)(rr + 8) * 4096 + cc] = make_float2(acc[mi][j][2], acc[mi][j][3]);
        }
}

__global__ __launch_bounds__(256, 1) void gemm_scores() {
    if (blockIdx.x > blockIdx.y) return;
    extern __shared__ char smem[];
    const int z = blockIdx.z, b = z >> 3, h = z & 7;
    const size_t base = (size_t)b * TT * 4096 + (size_t)h * 512;
    const int m0 = blockIdx.y * 128, n0 = blockIdx.x * 128;

    float acc[2][8][4];
    gemm_core(g_qh + base + (size_t)m0 * 4096, g_ql + base + (size_t)m0 * 4096, 4096,
              g_kh + base + (size_t)n0 * 4096, g_kl + base + (size_t)n0 * 4096, 4096,
              16, smem, acc);
    EPI_IDX();
    const float scale = 0.044194173824159216f;  // 1/sqrt(512)
    float* C = g_s + (size_t)z * TT * TT;
#pragma unroll
    for (int mi = 0; mi < 2; mi++)
#pragma unroll
        for (int j = 0; j < 8; j++) {
            const int cc = n0 + wn + j * 8 + ec;
#pragma unroll
            for (int half = 0; half < 2; half++) {
                const int rr = m0 + wm + mi * 16 + er + half * 8;
                float v0 = (cc > rr) ? -1e9f : acc[mi][j][2 * half] * scale;
                float v1 = (cc + 1 > rr) ? -1e9f : acc[mi][j][2 * half + 1] * scale;
                *(float2*)&C[(size_t)rr * 2048 + cc] = make_float2(v0, v1);
            }
        }
}

__global__ __launch_bounds__(256, 1) void gemm_av() {
    extern __shared__ char smem[];
    const int z = blockIdx.z, b = z >> 3, h = z & 7;
    const int m0 = blockIdx.y * 128;       // t block
    const int d0 = blockIdx.x * 128;       // d block
    const int nc = (blockIdx.y + 1) * 4;   // causal K limit (chunks of 32)
    const size_t pbase = (size_t)z * TT * TT + (size_t)m0 * 2048;
    const size_t vbase = ((size_t)z * 512 + d0) * 2048;

    float acc[2][8][4];
    gemm_core(g_ph + pbase, g_pl + pbase, 2048,
              g_vth + vbase, g_vtl + vbase, 2048,
              nc, smem, acc);
    EPI_IDX();
#pragma unroll
    for (int mi = 0; mi < 2; mi++)
#pragma unroll
        for (int j = 0; j < 8; j++) {
            const int cc = d0 + wn + j * 8 + ec;
#pragma unroll
            for (int half = 0; half < 2; half++) {
                const int rr = m0 + wm + mi * 16 + er + half * 8;
                const size_t o = (size_t)(b * TT + rr) * 4096 + h * 512 + cc;
                const float v0 = acc[mi][j][2 * half], v1 = acc[mi][j][2 * half + 1];
                const __nv_bfloat16 h0 = __float2bfloat16(v0);
                const __nv_bfloat16 h1 = __float2bfloat16(v1);
                const __nv_bfloat16 l0 = __float2bfloat16(v0 - __bfloat162float(h0));
                const __nv_bfloat16 l1 = __float2bfloat16(v1 - __bfloat162float(h1));
                *(__nv_bfloat162*)&g_oh[o] = __nv_bfloat162(h0, h1);
                *(__nv_bfloat162*)&g_ol[o] = __nv_bfloat162(l0, l1);
            }
        }
}

__global__ __launch_bounds__(256, 1) void gemm_oproj(float* __restrict__ out) {
    extern __shared__ char smem[];
    const int m0 = blockIdx.y * 128, n0 = blockIdx.x * 128;
    float acc[2][8][4];
    gemm_core(g_oh + (size_t)m0 * 4096, g_ol + (size_t)m0 * 4096, 4096,
              g_woh + (size_t)n0 * 4096, g_wol + (size_t)n0 * 4096, 4096,
              128, smem, acc);
    EPI_IDX();
#pragma unroll
    for (int mi = 0; mi < 2; mi++)
#pragma unroll
        for (int j = 0; j < 8; j++) {
            const int rr = m0 + wm + mi * 16 + er;
            const int cc = n0 + wn + j * 8 + ec;
            *(float2*)&out[(size_t)rr * 1024 + cc] = make_float2(acc[mi][j][0], acc[mi][j][1]);
            *(float2*)&out[(size_t)(rr + 8) * 1024 + cc] = make_float2(acc[mi][j][2], acc[mi][j][3]);
        }
}

// ---------------------------------------------------------------------------
// fp32 -> bf16 hi/lo split, elementwise (4 per thread)
// ---------------------------------------------------------------------------
__global__ __launch_bounds__(256) void conv_split(const float* __restrict__ s,
                                                  __nv_bfloat16* __restrict__ h,
                                                  __nv_bfloat16* __restrict__ l, int n) {
    const int i = (blockIdx.x * 256 + threadIdx.x) * 4;
    if (i >= n) return;
    float4 v = *(const float4*)(s + i);
    float f[4] = {v.x, v.y, v.z, v.w};
    __nv_bfloat16 hh[4], ll[4];
#pragma unroll
    for (int q = 0; q < 4; q++) {
        hh[q] = __float2bfloat16(f[q]);
        ll[q] = __float2bfloat16(f[q] - __bfloat162float(hh[q]));
    }
    *(__nv_bfloat162*)(h + i)     = __nv_bfloat162(hh[0], hh[1]);
    *(__nv_bfloat162*)(h + i + 2) = __nv_bfloat162(hh[2], hh[3]);
    *(__nv_bfloat162*)(l + i)     = __nv_bfloat162(ll[0], ll[1]);
    *(__nv_bfloat162*)(l + i + 2) = __nv_bfloat162(ll[2], ll[3]);
}

// ---------------------------------------------------------------------------
// RoPE + split:  reads g_q/g_k fp32, writes qh/ql/kh/kl bf16.
// ---------------------------------------------------------------------------
__global__ __launch_bounds__(256) void rope_conv() {
    const size_t gid = (size_t)blockIdx.x * 256 + threadIdx.x;
    const size_t half = 8388608ull;
    const bool isK = gid >= half;
    const size_t id = gid & (half - 1);
    const int row = (int)(id >> 11);
    const int p = (int)(id & 2047);
    const int h = p >> 8;
    const int i = p & 255;
    const int t = row & (TT - 1);

    const float expo = (float)(2 * i) * (1.0f / 512.0f);
    const float inv_f = 1.0f / powf(10000.0f, expo);
    const float ang = (float)t * inv_f;
    float sn, cs;
    sincosf(ang, &sn, &cs);

    const size_t idx = (size_t)row * 4096 + h * 512 + 2 * i;
    const float* src = isK ? g_k : g_q;
    __nv_bfloat16* dh = isK ? g_kh : g_qh;
    __nv_bfloat16* dl = isK ? g_kl : g_ql;
    const float x1 = src[idx], x2 = src[idx + 1];
    const float r1 = x1 * cs - x2 * sn;
    const float r2 = x1 * sn + x2 * cs;
    __nv_bfloat16 h1 = __float2bfloat16(r1), h2 = __float2bfloat16(r2);
    __nv_bfloat16 l1 = __float2bfloat16(r1 - __bfloat162float(h1));
    __nv_bfloat16 l2 = __float2bfloat16(r2 - __bfloat162float(h2));
    *(__nv_bfloat162*)(dh + idx) = __nv_bfloat162(h1, h2);
    *(__nv_bfloat162*)(dl + idx) = __nv_bfloat162(l1, l2);
}

// ---------------------------------------------------------------------------
// V transpose + split: g_v[(b,t),(h,d)] -> vt[(b,h), d, s] bf16 hi/lo
// ---------------------------------------------------------------------------
__global__ __launch_bounds__(256) void v_trans() {
    __shared__ float tile[32][33];
    const int z = blockIdx.z, b = z >> 3, h = z & 7;
    const int s0 = blockIdx.x * 32, d0 = blockIdx.y * 32;
    const int tx = threadIdx.x, ty = threadIdx.y;
#pragma unroll
    for (int i = 0; i < 4; i++) {
        const int s = s0 + ty + i * 8;
        tile[ty + i * 8][tx] = g_v[(size_t)(b * TT + s) * 4096 + h * 512 + d0 + tx];
    }
    __syncthreads();
#pragma unroll
    for (int i = 0; i < 4; i++) {
        const int d = d0 + ty + i * 8;
        const float f = tile[tx][ty + i * 8];
        __nv_bfloat16 hi = __float2bfloat16(f);
        __nv_bfloat16 lo = __float2bfloat16(f - __bfloat162float(hi));
        const size_t o = ((size_t)z * 512 + d) * 2048 + s0 + tx;
        g_vth[o] = hi;
        g_vtl[o] = lo;
    }
}

// ---------------------------------------------------------------------------
// Softmax: fp32 scores in, bf16 hi/lo probs out (zero-filled upper).
// ---------------------------------------------------------------------------
__global__ __launch_bounds__(256) void softmax2() {
    const int rI = blockIdx.x;
    const int t = rI & (TT - 1);
    float* row = g_s + (size_t)rI * TT;
    __nv_bfloat16* ph = g_ph + (size_t)rI * TT;
    __nv_bfloat16* pl = g_pl + (size_t)rI * TT;
    const int len = t + 1;
    const int tid = threadIdx.x;
    __shared__ float red[256];

    float m = -1e30f;
    for (int s = tid; s < len; s += 256) m = fmaxf(m, row[s]);
    red[tid] = m;
    __syncthreads();
#pragma unroll
    for (int off = 128; off > 0; off >>= 1) {
        if (tid < off) red[tid] = fmaxf(red[tid], red[tid + off]);
        __syncthreads();
    }
    m = red[0];
    __syncthreads();

    float sum = 0.f;
    for (int s = tid; s < len; s += 256) {
        const float e = expf(row[s] - m);
        row[s] = e;
        sum += e;
    }
    red[tid] = sum;
    __syncthreads();
#pragma unroll
    for (int off = 128; off > 0; off >>= 1) {
        if (tid < off) red[tid] += red[tid + off];
        __syncthreads();
    }
    const float inv = 1.0f / red[0];

    for (int s = tid; s < len; s += 256) {
        const float pv = row[s] * inv;
        __nv_bfloat16 hi = __float2bfloat16(pv);
        ph[s] = hi;
        pl[s] = __float2bfloat16(pv - __bfloat162float(hi));
    }
    const __nv_bfloat16 z0 = __float2bfloat16(0.f);
    for (int s = len + tid; s < TT; s += 256) { ph[s] = z0; pl[s] = z0; }
}

// ---------------------------------------------------------------------------
// Host orchestration
// ---------------------------------------------------------------------------
extern "C" void kernel_launch(void* const* d_in, const int* in_sizes, int n_in,
                              void* d_out, int out_size)
{
    const float* x  = (const float*)d_in[0];
    const float* wq = (const float*)d_in[1];
    const float* wk = (const float*)d_in[2];
    const float* wv = (const float*)d_in[3];
    const float* wo = (const float*)d_in[4];
    float* out = (float*)d_out;

    cudaFuncSetAttribute(gemm_qkv,    cudaFuncAttributeMaxDynamicSharedMemorySize, SMEM_BYTES);
    cudaFuncSetAttribute(gemm_scores, cudaFuncAttributeMaxDynamicSharedMemorySize, SMEM_BYTES);
    cudaFuncSetAttribute(gemm_av,     cudaFuncAttributeMaxDynamicSharedMemorySize, SMEM_BYTES);
    cudaFuncSetAttribute(gemm_oproj,  cudaFuncAttributeMaxDynamicSharedMemorySize, SMEM_BYTES);

    __nv_bfloat16 *xh, *xl, *wqh, *wql, *wkh, *wkl, *wvh, *wvl, *woh, *wol;
    cudaGetSymbolAddress((void**)&xh, g_xh);   cudaGetSymbolAddress((void**)&xl, g_xl);
    cudaGetSymbolAddress((void**)&wqh, g_wqh); cudaGetSymbolAddress((void**)&wql, g_wql);
    cudaGetSymbolAddress((void**)&wkh, g_wkh); cudaGetSymbolAddress((void**)&wkl, g_wkl);
    cudaGetSymbolAddress((void**)&wvh, g_wvh); cudaGetSymbolAddress((void**)&wvl, g_wvl);
    cudaGetSymbolAddress((void**)&woh, g_woh); cudaGetSymbolAddress((void**)&wol, g_wol);

    const int n4m = 4096 * 1024;
    conv_split<<<n4m / 1024, 256>>>(x,  xh,  xl,  n4m);
    conv_split<<<n4m / 1024, 256>>>(wq, wqh, wql, n4m);
    conv_split<<<n4m / 1024, 256>>>(wk, wkh, wkl, n4m);
    conv_split<<<n4m / 1024, 256>>>(wv, wvh, wvl, n4m);
    conv_split<<<n4m / 1024, 256>>>(wo, woh, wol, n4m);

    gemm_qkv<<<dim3(32, 32, 3), 256, SMEM_BYTES>>>();
    rope_conv<<<65536, 256>>>();
    v_trans<<<dim3(64, 16, 16), dim3(32, 8)>>>();
    gemm_scores<<<dim3(16, 16, 16), 256, SMEM_BYTES>>>();
    softmax2<<<32768, 256>>>();
    gemm_av<<<dim3(4, 16, 16), 256, SMEM_BYTES>>>();
    gemm_oproj<<<dim3(8, 32), 256, SMEM_BYTES>>>(out);
}

// round 6
// speedup vs baseline: 2.2580x; 1.1030x over previous
#include <cuda_runtime.h>
#include <cuda_bf16.h>
#include <math.h>
#include <stdint.h>

// Problem: B=2, T=2048, E=1024, H=8, D=512.  B*T=4096 rows, H*D=4096.
#define TT 2048

// ---------------------------------------------------------------------------
// Device scratch
// ---------------------------------------------------------------------------
__device__ float g_q[4096ull * 4096];            // fp32 Q (pre-rope)
__device__ float g_k[4096ull * 4096];            // fp32 K (pre-rope)
__device__ float g_v[4096ull * 4096];            // fp32 V
__device__ float g_s[16ull * 2048 * 2048];       // fp32 scores

__device__ __nv_bfloat16 g_xh[4096ull * 1024], g_xl[4096ull * 1024];
__device__ __nv_bfloat16 g_wqh[4096ull * 1024], g_wql[4096ull * 1024];
__device__ __nv_bfloat16 g_wkh[4096ull * 1024], g_wkl[4096ull * 1024];
__device__ __nv_bfloat16 g_wvh[4096ull * 1024], g_wvl[4096ull * 1024];
__device__ __nv_bfloat16 g_woh[1024ull * 4096], g_wol[1024ull * 4096];
__device__ __nv_bfloat16 g_qh[4096ull * 4096], g_ql[4096ull * 4096];
__device__ __nv_bfloat16 g_kh[4096ull * 4096], g_kl[4096ull * 4096];
__device__ __nv_bfloat16 g_vth[16ull * 512 * 2048], g_vtl[16ull * 512 * 2048];
__device__ __nv_bfloat16 g_ph[16ull * 2048 * 2048], g_pl[16ull * 2048 * 2048];
__device__ __nv_bfloat16 g_oh[4096ull * 4096], g_ol[4096ull * 4096];

// ---------------------------------------------------------------------------
// PTX helpers (arch-portable: cp.async / ldmatrix / mma.sync, all sm_80+)
// ---------------------------------------------------------------------------
__device__ __forceinline__ uint32_t s2u(const void* p) {
    uint32_t a;
    asm("{ .reg .u64 t; cvta.to.shared.u64 t, %1; cvt.u32.u64 %0, t; }" : "=r"(a) : "l"(p));
    return a;
}
__device__ __forceinline__ void cpa16(uint32_t dst, const void* src) {
    asm volatile("cp.async.cg.shared.global [%0], [%1], 16;" :: "r"(dst), "l"(src));
}
#define CP_COMMIT() asm volatile("cp.async.commit_group;" ::: "memory")
#define CP_WAIT(n)  asm volatile("cp.async.wait_group %0;" :: "n"(n) : "memory")

__device__ __forceinline__ void ldsm4(uint32_t* r, uint32_t addr) {
    asm volatile("ldmatrix.sync.aligned.m8n8.x4.shared.b16 {%0,%1,%2,%3}, [%4];"
                 : "=r"(r[0]), "=r"(r[1]), "=r"(r[2]), "=r"(r[3]) : "r"(addr));
}
__device__ __forceinline__ void mma16816(float* d, const uint32_t* a, const uint32_t* b) {
    asm volatile(
        "mma.sync.aligned.m16n8k16.row.col.f32.bf16.bf16.f32 "
        "{%0,%1,%2,%3}, {%4,%5,%6,%7}, {%8,%9}, {%0,%1,%2,%3};"
        : "+f"(d[0]), "+f"(d[1]), "+f"(d[2]), "+f"(d[3])
        : "r"(a[0]), "r"(a[1]), "r"(a[2]), "r"(a[3]), "r"(b[0]), "r"(b[1]));
}

// ---------------------------------------------------------------------------
// GEMM core: C[256,128] += (Ah+Al)[256,K] * (Bh+Bl)[128,K]^T, 3-combo split.
// BK=32, 3-stage cp.async ring, ONE __syncthreads per chunk.
// 8 warps: 4 in M x 2 in N; warp tile 64x64 -> 192 HMMA : 32 LDSM per chunk.
// Rows are 64B (32 bf16 K) with XOR swizzle: chunk' = chunk ^ ((row>>1)&3)
// -> conflict-free ldmatrix AND conflict-free cp.async stores.
// Stage layout: Ah@0 (16KB), Al@16384, Bh@32768 (8KB), Bl@40960. 48KB/stage.
// ---------------------------------------------------------------------------
#define STAGE_BYTES 49152
#define NSTAGE 3
#define SMEM_BYTES (NSTAGE * STAGE_BYTES)

__device__ __forceinline__ uint32_t swz64(int row, int chunk) {
    return row * 64 + ((chunk ^ ((row >> 1) & 3)) << 4);
}

__device__ __forceinline__ void stage_load(
    const __nv_bfloat16* __restrict__ ah, const __nv_bfloat16* __restrict__ al, int lda,
    const __nv_bfloat16* __restrict__ bh, const __nv_bfloat16* __restrict__ bl, int ldb,
    int k0, uint32_t sdst)
{
    const int tid = threadIdx.x;
#pragma unroll
    for (int i = 0; i < 12; i++) {
        const int idx = tid + i * 256;        // 0..3071 16B-chunks
        const __nv_bfloat16* src;
        int ld, local;
        uint32_t rbase;
        if (idx < 1024)      { local = idx;        src = ah; ld = lda; rbase = 0; }
        else if (idx < 2048) { local = idx - 1024; src = al; ld = lda; rbase = 16384; }
        else if (idx < 2560) { local = idx - 2048; src = bh; ld = ldb; rbase = 32768; }
        else                 { local = idx - 2560; src = bl; ld = ldb; rbase = 40960; }
        const int row = local >> 2, c = local & 3;
        cpa16(sdst + rbase + swz64(row, c), src + (size_t)row * ld + k0 + c * 8);
    }
}

__device__ __forceinline__ void stage_compute(uint32_t sb, float acc[4][8][4]) {
    const int lane = threadIdx.x & 31;
    const int wid = threadIdx.x >> 5;
    const int wm = (wid & 3) * 64;
    const int wn = (wid >> 2) * 64;
    const int lr = lane & 15;
    const int hc = lane >> 4;
#pragma unroll
    for (int kk = 0; kk < 2; kk++) {
        const int chunk = kk * 2 + hc;
        uint32_t Ah[4][4], Al[4][4], Bh[8][2], Bl[8][2];
#pragma unroll
        for (int mi = 0; mi < 4; mi++) {
            const uint32_t ad = sb + swz64(wm + mi * 16 + lr, chunk);
            ldsm4(Ah[mi], ad);
            ldsm4(Al[mi], ad + 16384);
        }
#pragma unroll
        for (int jj = 0; jj < 4; jj++) {
            const uint32_t bd = sb + 32768 + swz64(wn + jj * 16 + lr, chunk);
            uint32_t t[4];
            ldsm4(t, bd);
            Bh[2 * jj][0] = t[0]; Bh[2 * jj][1] = t[2];
            Bh[2 * jj + 1][0] = t[1]; Bh[2 * jj + 1][1] = t[3];
            ldsm4(t, bd + 8192);
            Bl[2 * jj][0] = t[0]; Bl[2 * jj][1] = t[2];
            Bl[2 * jj + 1][0] = t[1]; Bl[2 * jj + 1][1] = t[3];
        }
#pragma unroll
        for (int mi = 0; mi < 4; mi++)
#pragma unroll
            for (int j = 0; j < 8; j++) {
                mma16816(acc[mi][j], Ah[mi], Bh[j]);
                mma16816(acc[mi][j], Ah[mi], Bl[j]);
                mma16816(acc[mi][j], Al[mi], Bh[j]);
            }
    }
}

// nc must be >= 2 (all call sites have nc >= 8).
__device__ __forceinline__ void gemm_core(
    const __nv_bfloat16* ah, const __nv_bfloat16* al, int lda,
    const __nv_bfloat16* bh, const __nv_bfloat16* bl, int ldb,
    int nc, char* smem, float acc[4][8][4])
{
    const uint32_t sb = s2u(smem);
#pragma unroll
    for (int mi = 0; mi < 4; mi++)
#pragma unroll
        for (int j = 0; j < 8; j++)
#pragma unroll
            for (int q = 0; q < 4; q++) acc[mi][j][q] = 0.f;

    stage_load(ah, al, lda, bh, bl, ldb, 0, sb);
    CP_COMMIT();
    stage_load(ah, al, lda, bh, bl, ldb, 32, sb + STAGE_BYTES);
    CP_COMMIT();

    int cur = 0, pre = 2;   // compute buffer, prefetch buffer (c%3, (c+2)%3)
    for (int c = 0; c < nc; c++) {
        if (c < nc - 1) { CP_WAIT(1); } else { CP_WAIT(0); }
        __syncthreads();
        stage_compute(sb + cur * STAGE_BYTES, acc);
        // Prefetch chunk c+2 into buffer (c+2)%3 = (c-1)%3, whose readers all
        // passed this iteration's barrier. No second barrier needed.
        if (c + 2 < nc) {
            stage_load(ah, al, lda, bh, bl, ldb, (c + 2) * 32, sb + pre * STAGE_BYTES);
            CP_COMMIT();
        }
        if (++cur == 3) cur = 0;
        if (++pre == 3) pre = 0;
    }
}

// Epilogue index helpers (per warp/lane)
#define EPI_IDX()                                   \
    const int lane = threadIdx.x & 31;              \
    const int wid = threadIdx.x >> 5;               \
    const int wm = (wid & 3) * 64;                  \
    const int wn = (wid >> 2) * 64;                 \
    const int er = lane >> 2;                       \
    const int ec = (lane & 3) * 2;

// ---------------------------------------------------------------------------
// GEMM kernels (block tile 256x128)
// ---------------------------------------------------------------------------
__global__ __launch_bounds__(256, 1) void gemm_qkv() {
    extern __shared__ char smem[];
    const int m0 = blockIdx.y * 256, n0 = blockIdx.x * 128;
    const int z = blockIdx.z;
    const __nv_bfloat16* bh = (z == 0) ? g_wqh : (z == 1) ? g_wkh : g_wvh;
    const __nv_bfloat16* bl = (z == 0) ? g_wql : (z == 1) ? g_wkl : g_wvl;
    float* C = (z == 0) ? g_q : (z == 1) ? g_k : g_v;

    float acc[4][8][4];
    gemm_core(g_xh + (size_t)m0 * 1024, g_xl + (size_t)m0 * 1024, 1024,
              bh + (size_t)n0 * 1024, bl + (size_t)n0 * 1024, 1024,
              32, smem, acc);
    EPI_IDX();
#pragma unroll
    for (int mi = 0; mi < 4; mi++)
#pragma unroll
        for (int j = 0; j < 8; j++) {
            const int rr = m0 + wm + mi * 16 + er;
            const int cc = n0 + wn + j * 8 + ec;
            *(float2*)&C[(size_t)rr * 4096 + cc] = make_float2(acc[mi][j][0], acc[mi][j][1]);
            *(float2*)&C[(size_t)(rr + 8) * 4096 + cc] = make_float2(acc[mi][j][2], acc[mi][j][3]);
        }
}

__global__ __launch_bounds__(256, 1) void gemm_scores() {
    if ((int)blockIdx.x > 2 * (int)blockIdx.y + 1) return;   // fully-masked block
    extern __shared__ char smem[];
    const int z = blockIdx.z, b = z >> 3, h = z & 7;
    const size_t base = (size_t)b * TT * 4096 + (size_t)h * 512;
    const int m0 = blockIdx.y * 256, n0 = blockIdx.x * 128;

    float acc[4][8][4];
    gemm_core(g_qh + base + (size_t)m0 * 4096, g_ql + base + (size_t)m0 * 4096, 4096,
              g_kh + base + (size_t)n0 * 4096, g_kl + base + (size_t)n0 * 4096, 4096,
              16, smem, acc);
    EPI_IDX();
    const float scale = 0.044194173824159216f;  // 1/sqrt(512)
    float* C = g_s + (size_t)z * TT * TT;
#pragma unroll
    for (int mi = 0; mi < 4; mi++)
#pragma unroll
        for (int j = 0; j < 8; j++) {
            const int cc = n0 + wn + j * 8 + ec;
#pragma unroll
            for (int half = 0; half < 2; half++) {
                const int rr = m0 + wm + mi * 16 + er + half * 8;
                float v0 = (cc > rr) ? -1e9f : acc[mi][j][2 * half] * scale;
                float v1 = (cc + 1 > rr) ? -1e9f : acc[mi][j][2 * half + 1] * scale;
                *(float2*)&C[(size_t)rr * 2048 + cc] = make_float2(v0, v1);
            }
        }
}

__global__ __launch_bounds__(256, 1) void gemm_av() {
    extern __shared__ char smem[];
    const int z = blockIdx.z, b = z >> 3, h = z & 7;
    const int m0 = blockIdx.y * 256;       // t block
    const int d0 = blockIdx.x * 128;       // d block
    const int nc = (blockIdx.y + 1) * 8;   // causal K limit (chunks of 32)
    const size_t pbase = (size_t)z * TT * TT + (size_t)m0 * 2048;
    const size_t vbase = ((size_t)z * 512 + d0) * 2048;

    float acc[4][8][4];
    gemm_core(g_ph + pbase, g_pl + pbase, 2048,
              g_vth + vbase, g_vtl + vbase, 2048,
              nc, smem, acc);
    EPI_IDX();
#pragma unroll
    for (int mi = 0; mi < 4; mi++)
#pragma unroll
        for (int j = 0; j < 8; j++) {
            const int cc = d0 + wn + j * 8 + ec;
#pragma unroll
            for (int half = 0; half < 2; half++) {
                const int rr = m0 + wm + mi * 16 + er + half * 8;
                const size_t o = (size_t)(b * TT + rr) * 4096 + h * 512 + cc;
                const float v0 = acc[mi][j][2 * half], v1 = acc[mi][j][2 * half + 1];
                const __nv_bfloat16 h0 = __float2bfloat16(v0);
                const __nv_bfloat16 h1 = __float2bfloat16(v1);
                const __nv_bfloat16 l0 = __float2bfloat16(v0 - __bfloat162float(h0));
                const __nv_bfloat16 l1 = __float2bfloat16(v1 - __bfloat162float(h1));
                *(__nv_bfloat162*)&g_oh[o] = __nv_bfloat162(h0, h1);
                *(__nv_bfloat162*)&g_ol[o] = __nv_bfloat162(l0, l1);
            }
        }
}

__global__ __launch_bounds__(256, 1) void gemm_oproj(float* __restrict__ out) {
    extern __shared__ char smem[];
    const int m0 = blockIdx.y * 256, n0 = blockIdx.x * 128;
    float acc[4][8][4];
    gemm_core(g_oh + (size_t)m0 * 4096, g_ol + (size_t)m0 * 4096, 4096,
              g_woh + (size_t)n0 * 4096, g_wol + (size_t)n0 * 4096, 4096,
              128, smem, acc);
    EPI_IDX();
#pragma unroll
    for (int mi = 0; mi < 4; mi++)
#pragma unroll
        for (int j = 0; j < 8; j++) {
            const int rr = m0 + wm + mi * 16 + er;
            const int cc = n0 + wn + j * 8 + ec;
            *(float2*)&out[(size_t)rr * 1024 + cc] = make_float2(acc[mi][j][0], acc[mi][j][1]);
            *(float2*)&out[(size_t)(rr + 8) * 1024 + cc] = make_float2(acc[mi][j][2], acc[mi][j][3]);
        }
}

// ---------------------------------------------------------------------------
// fp32 -> bf16 hi/lo split, elementwise (4 per thread)
// ---------------------------------------------------------------------------
__global__ __launch_bounds__(256) void conv_split(const float* __restrict__ s,
                                                  __nv_bfloat16* __restrict__ h,
                                                  __nv_bfloat16* __restrict__ l, int n) {
    const int i = (blockIdx.x * 256 + threadIdx.x) * 4;
    if (i >= n) return;
    float4 v = *(const float4*)(s + i);
    float f[4] = {v.x, v.y, v.z, v.w};
    __nv_bfloat16 hh[4], ll[4];
#pragma unroll
    for (int q = 0; q < 4; q++) {
        hh[q] = __float2bfloat16(f[q]);
        ll[q] = __float2bfloat16(f[q] - __bfloat162float(hh[q]));
    }
    *(__nv_bfloat162*)(h + i)     = __nv_bfloat162(hh[0], hh[1]);
    *(__nv_bfloat162*)(h + i + 2) = __nv_bfloat162(hh[2], hh[3]);
    *(__nv_bfloat162*)(l + i)     = __nv_bfloat162(ll[0], ll[1]);
    *(__nv_bfloat162*)(l + i + 2) = __nv_bfloat162(ll[2], ll[3]);
}

// ---------------------------------------------------------------------------
// RoPE + split:  reads g_q/g_k fp32, writes qh/ql/kh/kl bf16.
// ---------------------------------------------------------------------------
__global__ __launch_bounds__(256) void rope_conv() {
    const size_t gid = (size_t)blockIdx.x * 256 + threadIdx.x;
    const size_t half = 8388608ull;
    const bool isK = gid >= half;
    const size_t id = gid & (half - 1);
    const int row = (int)(id >> 11);
    const int p = (int)(id & 2047);
    const int h = p >> 8;
    const int i = p & 255;
    const int t = row & (TT - 1);

    const float expo = (float)(2 * i) * (1.0f / 512.0f);
    const float inv_f = 1.0f / powf(10000.0f, expo);
    const float ang = (float)t * inv_f;
    float sn, cs;
    sincosf(ang, &sn, &cs);

    const size_t idx = (size_t)row * 4096 + h * 512 + 2 * i;
    const float* src = isK ? g_k : g_q;
    __nv_bfloat16* dh = isK ? g_kh : g_qh;
    __nv_bfloat16* dl = isK ? g_kl : g_ql;
    const float x1 = src[idx], x2 = src[idx + 1];
    const float r1 = x1 * cs - x2 * sn;
    const float r2 = x1 * sn + x2 * cs;
    __nv_bfloat16 h1 = __float2bfloat16(r1), h2 = __float2bfloat16(r2);
    __nv_bfloat16 l1 = __float2bfloat16(r1 - __bfloat162float(h1));
    __nv_bfloat16 l2 = __float2bfloat16(r2 - __bfloat162float(h2));
    *(__nv_bfloat162*)(dh + idx) = __nv_bfloat162(h1, h2);
    *(__nv_bfloat162*)(dl + idx) = __nv_bfloat162(l1, l2);
}

// ---------------------------------------------------------------------------
// V transpose + split: g_v[(b,t),(h,d)] -> vt[(b,h), d, s] bf16 hi/lo
// ---------------------------------------------------------------------------
__global__ __launch_bounds__(256) void v_trans() {
    __shared__ float tile[32][33];
    const int z = blockIdx.z, b = z >> 3, h = z & 7;
    const int s0 = blockIdx.x * 32, d0 = blockIdx.y * 32;
    const int tx = threadIdx.x, ty = threadIdx.y;
#pragma unroll
    for (int i = 0; i < 4; i++) {
        const int s = s0 + ty + i * 8;
        tile[ty + i * 8][tx] = g_v[(size_t)(b * TT + s) * 4096 + h * 512 + d0 + tx];
    }
    __syncthreads();
#pragma unroll
    for (int i = 0; i < 4; i++) {
        const int d = d0 + ty + i * 8;
        const float f = tile[tx][ty + i * 8];
        __nv_bfloat16 hi = __float2bfloat16(f);
        __nv_bfloat16 lo = __float2bfloat16(f - __bfloat162float(hi));
        const size_t o = ((size_t)z * 512 + d) * 2048 + s0 + tx;
        g_vth[o] = hi;
        g_vtl[o] = lo;
    }
}

// ---------------------------------------------------------------------------
// Softmax: fp32 scores in, bf16 hi/lo probs out (zero-filled upper).
// ---------------------------------------------------------------------------
__global__ __launch_bounds__(256) void softmax2() {
    const int rI = blockIdx.x;
    const int t = rI & (TT - 1);
    float* row = g_s + (size_t)rI * TT;
    __nv_bfloat16* ph = g_ph + (size_t)rI * TT;
    __nv_bfloat16* pl = g_pl + (size_t)rI * TT;
    const int len = t + 1;
    const int tid = threadIdx.x;
    __shared__ float red[256];

    float m = -1e30f;
    for (int s = tid; s < len; s += 256) m = fmaxf(m, row[s]);
    red[tid] = m;
    __syncthreads();
#pragma unroll
    for (int off = 128; off > 0; off >>= 1) {
        if (tid < off) red[tid] = fmaxf(red[tid], red[tid + off]);
        __syncthreads();
    }
    m = red[0];
    __syncthreads();

    float sum = 0.f;
    for (int s = tid; s < len; s += 256) {
        const float e = expf(row[s] - m);
        row[s] = e;
        sum += e;
    }
    red[tid] = sum;
    __syncthreads();
#pragma unroll
    for (int off = 128; off > 0; off >>= 1) {
        if (tid < off) red[tid] += red[tid + off];
        __syncthreads();
    }
    const float inv = 1.0f / red[0];

    for (int s = tid; s < len; s += 256) {
        const float pv = row[s] * inv;
        __nv_bfloat16 hi = __float2bfloat16(pv);
        ph[s] = hi;
        pl[s] = __float2bfloat16(pv - __bfloat162float(hi));
    }
    const __nv_bfloat16 z0 = __float2bfloat16(0.f);
    for (int s = len + tid; s < TT; s += 256) { ph[s] = z0; pl[s] = z0; }
}

// ---------------------------------------------------------------------------
// Host orchestration
// ---------------------------------------------------------------------------
extern "C" void kernel_launch(void* const* d_in, const int* in_sizes, int n_in,
                              void* d_out, int out_size)
{
    const float* x  = (const float*)d_in[0];
    const float* wq = (const float*)d_in[1];
    const float* wk = (const float*)d_in[2];
    const float* wv = (const float*)d_in[3];
    const float* wo = (const float*)d_in[4];
    float* out = (float*)d_out;

    cudaFuncSetAttribute(gemm_qkv,    cudaFuncAttributeMaxDynamicSharedMemorySize, SMEM_BYTES);
    cudaFuncSetAttribute(gemm_scores, cudaFuncAttributeMaxDynamicSharedMemorySize, SMEM_BYTES);
    cudaFuncSetAttribute(gemm_av,     cudaFuncAttributeMaxDynamicSharedMemorySize, SMEM_BYTES);
    cudaFuncSetAttribute(gemm_oproj,  cudaFuncAttributeMaxDynamicSharedMemorySize, SMEM_BYTES);

    __nv_bfloat16 *xh, *xl, *wqh, *wql, *wkh, *wkl, *wvh, *wvl, *woh, *wol;
    cudaGetSymbolAddress((void**)&xh, g_xh);   cudaGetSymbolAddress((void**)&xl, g_xl);
    cudaGetSymbolAddress((void**)&wqh, g_wqh); cudaGetSymbolAddress((void**)&wql, g_wql);
    cudaGetSymbolAddress((void**)&wkh, g_wkh); cudaGetSymbolAddress((void**)&wkl, g_wkl);
    cudaGetSymbolAddress((void**)&wvh, g_wvh); cudaGetSymbolAddress((void**)&wvl, g_wvl);
    cudaGetSymbolAddress((void**)&woh, g_woh); cudaGetSymbolAddress((void**)&wol, g_wol);

    const int n4m = 4096 * 1024;
    conv_split<<<n4m / 1024, 256>>>(x,  xh,  xl,  n4m);
    conv_split<<<n4m / 1024, 256>>>(wq, wqh, wql, n4m);
    conv_split<<<n4m / 1024, 256>>>(wk, wkh, wkl, n4m);
    conv_split<<<n4m / 1024, 256>>>(wv, wvh, wvl, n4m);
    conv_split<<<n4m / 1024, 256>>>(wo, woh, wol, n4m);

    gemm_qkv<<<dim3(32, 16, 3), 256, SMEM_BYTES>>>();
    rope_conv<<<65536, 256>>>();
    v_trans<<<dim3(64, 16, 16), dim3(32, 8)>>>();
    gemm_scores<<<dim3(16, 8, 16), 256, SMEM_BYTES>>>();
    softmax2<<<32768, 256>>>();
    gemm_av<<<dim3(4, 8, 16), 256, SMEM_BYTES>>>();
    gemm_oproj<<<dim3(8, 16), 256, SMEM_BYTES>>>(out);
}

// round 8
// speedup vs baseline: 2.6384x; 1.1685x over previous
#include <cuda_runtime.h>
#include <cuda_fp16.h>
#include <math.h>
#include <stdint.h>

// Problem: B=2, T=2048, E=1024, H=8, D=512.  B*T=4096 rows, H*D=4096.
#define TT 2048

// ---------------------------------------------------------------------------
// Device scratch
// ---------------------------------------------------------------------------
__device__ float g_q[4096ull * 4096];            // fp32 Q (pre-rope)
__device__ float g_k[4096ull * 4096];            // fp32 K (pre-rope)
__device__ float g_v[4096ull * 4096];            // fp32 V
__device__ float g_s[16ull * 2048 * 2048];       // fp32 scores

__device__ __half g_xh[4096ull * 1024];
__device__ __half g_wqh[4096ull * 1024], g_wql[4096ull * 1024];
__device__ __half g_wkh[4096ull * 1024], g_wkl[4096ull * 1024];
__device__ __half g_wvh[4096ull * 1024], g_wvl[4096ull * 1024];
__device__ __half g_woh[1024ull * 4096], g_wol[1024ull * 4096];
__device__ __half g_qh[4096ull * 4096], g_ql[4096ull * 4096];
__device__ __half g_kh[4096ull * 4096], g_kl[4096ull * 4096];
__device__ __half g_vth[16ull * 512 * 2048], g_vtl[16ull * 512 * 2048];
__device__ __half g_ph[16ull * 2048 * 2048], g_pl[16ull * 2048 * 2048];
__device__ __half g_oh[4096ull * 4096], g_ol[4096ull * 4096];

// ---------------------------------------------------------------------------
// PTX helpers (arch-portable: cp.async / ldmatrix / mma.sync, all sm_80+)
// ---------------------------------------------------------------------------
__device__ __forceinline__ uint32_t s2u(const void* p) {
    uint32_t a;
    asm("{ .reg .u64 t; cvta.to.shared.u64 t, %1; cvt.u32.u64 %0, t; }" : "=r"(a) : "l"(p));
    return a;
}
__device__ __forceinline__ void cpa16(uint32_t dst, const void* src) {
    asm volatile("cp.async.cg.shared.global [%0], [%1], 16;" :: "r"(dst), "l"(src));
}
#define CP_COMMIT() asm volatile("cp.async.commit_group;" ::: "memory")
#define CP_WAIT(n)  asm volatile("cp.async.wait_group %0;" :: "n"(n) : "memory")

__device__ __forceinline__ void ldsm4(uint32_t* r, uint32_t addr) {
    asm volatile("ldmatrix.sync.aligned.m8n8.x4.shared.b16 {%0,%1,%2,%3}, [%4];"
                 : "=r"(r[0]), "=r"(r[1]), "=r"(r[2]), "=r"(r[3]) : "r"(addr));
}
__device__ __forceinline__ void mma16816(float* d, const uint32_t* a, const uint32_t* b) {
    asm volatile(
        "mma.sync.aligned.m16n8k16.row.col.f32.f16.f16.f32 "
        "{%0,%1,%2,%3}, {%4,%5,%6,%7}, {%8,%9}, {%0,%1,%2,%3};"
        : "+f"(d[0]), "+f"(d[1]), "+f"(d[2]), "+f"(d[3])
        : "r"(a[0]), "r"(a[1]), "r"(a[2]), "r"(a[3]), "r"(b[0]), "r"(b[1]));
}

__device__ __forceinline__ __half2 split_hi2(float a, float b, __half& la, __half& lb) {
    __half ha = __float2half_rn(a), hb = __float2half_rn(b);
    la = __float2half_rn(a - __half2float(ha));
    lb = __float2half_rn(b - __half2float(hb));
    return __halves2half2(ha, hb);
}

// ---------------------------------------------------------------------------
// Swizzled 64B-row layout: chunk' = chunk ^ ((row>>1)&3); conflict-free for
// ldmatrix and cp.async stores. Block tile 256x128, 8 warps (4M x 2N),
// warp tile 64x64. 3-stage cp.async ring, one __syncthreads per chunk.
// 3-combo variant: Ah@0, Al@16384, Bh@32768, Bl@40960 (48KB/stage).
// 2-combo variant: Ah@0, Bh@16384, Bl@24576 (32KB/stage).
// ---------------------------------------------------------------------------
#define STAGE3_BYTES 49152
#define STAGE2_BYTES 32768
#define SMEM3_BYTES (3 * STAGE3_BYTES)
#define SMEM2_BYTES (3 * STAGE2_BYTES)

__device__ __forceinline__ uint32_t swz64(int row, int chunk) {
    return row * 64 + ((chunk ^ ((row >> 1) & 3)) << 4);
}

// ---- 3-combo (hi/lo on both sides): AhBh + AhBl + AlBh ----
__device__ __forceinline__ void stage_load3(
    const __half* __restrict__ ah, const __half* __restrict__ al, int lda,
    const __half* __restrict__ bh, const __half* __restrict__ bl, int ldb,
    int k0, uint32_t sdst)
{
    const int tid = threadIdx.x;
#pragma unroll
    for (int i = 0; i < 12; i++) {
        const int idx = tid + i * 256;
        const __half* src;
        int ld, local;
        uint32_t rbase;
        if (idx < 1024)      { local = idx;        src = ah; ld = lda; rbase = 0; }
        else if (idx < 2048) { local = idx - 1024; src = al; ld = lda; rbase = 16384; }
        else if (idx < 2560) { local = idx - 2048; src = bh; ld = ldb; rbase = 32768; }
        else                 { local = idx - 2560; src = bl; ld = ldb; rbase = 40960; }
        const int row = local >> 2, c = local & 3;
        cpa16(sdst + rbase + swz64(row, c), src + (size_t)row * ld + k0 + c * 8);
    }
}

__device__ __forceinline__ void stage_compute3(uint32_t sb, float acc[4][8][4]) {
    const int lane = threadIdx.x & 31;
    const int wid = threadIdx.x >> 5;
    const int wm = (wid & 3) * 64;
    const int wn = (wid >> 2) * 64;
    const int lr = lane & 15;
    const int hc = lane >> 4;
#pragma unroll
    for (int kk = 0; kk < 2; kk++) {
        const int chunk = kk * 2 + hc;
        uint32_t Ah[4][4], Al[4][4], Bh[8][2], Bl[8][2];
#pragma unroll
        for (int mi = 0; mi < 4; mi++) {
            const uint32_t ad = sb + swz64(wm + mi * 16 + lr, chunk);
            ldsm4(Ah[mi], ad);
            ldsm4(Al[mi], ad + 16384);
        }
#pragma unroll
        for (int jj = 0; jj < 4; jj++) {
            const uint32_t bd = sb + 32768 + swz64(wn + jj * 16 + lr, chunk);
            uint32_t t[4];
            ldsm4(t, bd);
            Bh[2 * jj][0] = t[0]; Bh[2 * jj][1] = t[2];
            Bh[2 * jj + 1][0] = t[1]; Bh[2 * jj + 1][1] = t[3];
            ldsm4(t, bd + 8192);
            Bl[2 * jj][0] = t[0]; Bl[2 * jj][1] = t[2];
            Bl[2 * jj + 1][0] = t[1]; Bl[2 * jj + 1][1] = t[3];
        }
#pragma unroll
        for (int mi = 0; mi < 4; mi++)
#pragma unroll
            for (int j = 0; j < 8; j++) {
                mma16816(acc[mi][j], Ah[mi], Bh[j]);
                mma16816(acc[mi][j], Ah[mi], Bl[j]);
                mma16816(acc[mi][j], Al[mi], Bh[j]);
            }
    }
}

__device__ __forceinline__ void gemm_core3(
    const __half* ah, const __half* al, int lda,
    const __half* bh, const __half* bl, int ldb,
    int nc, char* smem, float acc[4][8][4])
{
    const uint32_t sb = s2u(smem);
#pragma unroll
    for (int mi = 0; mi < 4; mi++)
#pragma unroll
        for (int j = 0; j < 8; j++)
#pragma unroll
            for (int q = 0; q < 4; q++) acc[mi][j][q] = 0.f;

    stage_load3(ah, al, lda, bh, bl, ldb, 0, sb);
    CP_COMMIT();
    stage_load3(ah, al, lda, bh, bl, ldb, 32, sb + STAGE3_BYTES);
    CP_COMMIT();
    int cur = 0, pre = 2;
    for (int c = 0; c < nc; c++) {
        if (c < nc - 1) { CP_WAIT(1); } else { CP_WAIT(0); }
        __syncthreads();
        stage_compute3(sb + cur * STAGE3_BYTES, acc);
        if (c + 2 < nc) {
            stage_load3(ah, al, lda, bh, bl, ldb, (c + 2) * 32, sb + pre * STAGE3_BYTES);
            CP_COMMIT();
        }
        if (++cur == 3) cur = 0;
        if (++pre == 3) pre = 0;
    }
}

// ---- 2-combo (A hi-only): AhBh + AhBl ----
__device__ __forceinline__ void stage_load2(
    const __half* __restrict__ ah, int lda,
    const __half* __restrict__ bh, const __half* __restrict__ bl, int ldb,
    int k0, uint32_t sdst)
{
    const int tid = threadIdx.x;
#pragma unroll
    for (int i = 0; i < 8; i++) {
        const int idx = tid + i * 256;
        const __half* src;
        int ld, local;
        uint32_t rbase;
        if (idx < 1024)      { local = idx;        src = ah; ld = lda; rbase = 0; }
        else if (idx < 1536) { local = idx - 1024; src = bh; ld = ldb; rbase = 16384; }
        else                 { local = idx - 1536; src = bl; ld = ldb; rbase = 24576; }
        const int row = local >> 2, c = local & 3;
        cpa16(sdst + rbase + swz64(row, c), src + (size_t)row * ld + k0 + c * 8);
    }
}

__device__ __forceinline__ void stage_compute2(uint32_t sb, float acc[4][8][4]) {
    const int lane = threadIdx.x & 31;
    const int wid = threadIdx.x >> 5;
    const int wm = (wid & 3) * 64;
    const int wn = (wid >> 2) * 64;
    const int lr = lane & 15;
    const int hc = lane >> 4;
#pragma unroll
    for (int kk = 0; kk < 2; kk++) {
        const int chunk = kk * 2 + hc;
        uint32_t Ah[4][4], Bh[8][2], Bl[8][2];
#pragma unroll
        for (int mi = 0; mi < 4; mi++)
            ldsm4(Ah[mi], sb + swz64(wm + mi * 16 + lr, chunk));
#pragma unroll
        for (int jj = 0; jj < 4; jj++) {
            const uint32_t bd = sb + 16384 + swz64(wn + jj * 16 + lr, chunk);
            uint32_t t[4];
            ldsm4(t, bd);
            Bh[2 * jj][0] = t[0]; Bh[2 * jj][1] = t[2];
            Bh[2 * jj + 1][0] = t[1]; Bh[2 * jj + 1][1] = t[3];
            ldsm4(t, bd + 8192);
            Bl[2 * jj][0] = t[0]; Bl[2 * jj][1] = t[2];
            Bl[2 * jj + 1][0] = t[1]; Bl[2 * jj + 1][1] = t[3];
        }
#pragma unroll
        for (int mi = 0; mi < 4; mi++)
#pragma unroll
            for (int j = 0; j < 8; j++) {
                mma16816(acc[mi][j], Ah[mi], Bh[j]);
                mma16816(acc[mi][j], Ah[mi], Bl[j]);
            }
    }
}

__device__ __forceinline__ void gemm_core2(
    const __half* ah, int lda,
    const __half* bh, const __half* bl, int ldb,
    int nc, char* smem, float acc[4][8][4])
{
    const uint32_t sb = s2u(smem);
#pragma unroll
    for (int mi = 0; mi < 4; mi++)
#pragma unroll
        for (int j = 0; j < 8; j++)
#pragma unroll
            for (int q = 0; q < 4; q++) acc[mi][j][q] = 0.f;

    stage_load2(ah, lda, bh, bl, ldb, 0, sb);
    CP_COMMIT();
    stage_load2(ah, lda, bh, bl, ldb, 32, sb + STAGE2_BYTES);
    CP_COMMIT();
    int cur = 0, pre = 2;
    for (int c = 0; c < nc; c++) {
        if (c < nc - 1) { CP_WAIT(1); } else { CP_WAIT(0); }
        __syncthreads();
        stage_compute2(sb + cur * STAGE2_BYTES, acc);
        if (c + 2 < nc) {
            stage_load2(ah, lda, bh, bl, ldb, (c + 2) * 32, sb + pre * STAGE2_BYTES);
            CP_COMMIT();
        }
        if (++cur == 3) cur = 0;
        if (++pre == 3) pre = 0;
    }
}

// Epilogue index helpers (per warp/lane)
#define EPI_IDX()                                   \
    const int lane = threadIdx.x & 31;              \
    const int wid = threadIdx.x >> 5;               \
    const int wm = (wid & 3) * 64;                  \
    const int wn = (wid >> 2) * 64;                 \
    const int er = lane >> 2;                       \
    const int ec = (lane & 3) * 2;

// ---------------------------------------------------------------------------
// GEMM kernels (block tile 256x128)
// ---------------------------------------------------------------------------
__global__ __launch_bounds__(256, 1) void gemm_qkv() {
    extern __shared__ char smem[];
    const int m0 = blockIdx.y * 256, n0 = blockIdx.x * 128;
    const int z = blockIdx.z;
    const __half* bh = (z == 0) ? g_wqh : (z == 1) ? g_wkh : g_wvh;
    const __half* bl = (z == 0) ? g_wql : (z == 1) ? g_wkl : g_wvl;
    float* C = (z == 0) ? g_q : (z == 1) ? g_k : g_v;

    float acc[4][8][4];
    gemm_core2(g_xh + (size_t)m0 * 1024, 1024,
               bh + (size_t)n0 * 1024, bl + (size_t)n0 * 1024, 1024,
               32, smem, acc);
    EPI_IDX();
#pragma unroll
    for (int mi = 0; mi < 4; mi++)
#pragma unroll
        for (int j = 0; j < 8; j++) {
            const int rr = m0 + wm + mi * 16 + er;
            const int cc = n0 + wn + j * 8 + ec;
            *(float2*)&C[(size_t)rr * 4096 + cc] = make_float2(acc[mi][j][0], acc[mi][j][1]);
            *(float2*)&C[(size_t)(rr + 8) * 4096 + cc] = make_float2(acc[mi][j][2], acc[mi][j][3]);
        }
}

__global__ __launch_bounds__(256, 1) void gemm_scores() {
    if ((int)blockIdx.x > 2 * (int)blockIdx.y + 1) return;   // fully-masked block
    extern __shared__ char smem[];
    const int z = blockIdx.z, b = z >> 3, h = z & 7;
    const size_t base = (size_t)b * TT * 4096 + (size_t)h * 512;
    const int m0 = blockIdx.y * 256, n0 = blockIdx.x * 128;

    float acc[4][8][4];
    gemm_core3(g_qh + base + (size_t)m0 * 4096, g_ql + base + (size_t)m0 * 4096, 4096,
               g_kh + base + (size_t)n0 * 4096, g_kl + base + (size_t)n0 * 4096, 4096,
               16, smem, acc);
    EPI_IDX();
    const float scale = 0.044194173824159216f;  // 1/sqrt(512)
    float* C = g_s + (size_t)z * TT * TT;
#pragma unroll
    for (int mi = 0; mi < 4; mi++)
#pragma unroll
        for (int j = 0; j < 8; j++) {
            const int cc = n0 + wn + j * 8 + ec;
#pragma unroll
            for (int half = 0; half < 2; half++) {
                const int rr = m0 + wm + mi * 16 + er + half * 8;
                float v0 = (cc > rr) ? -1e9f : acc[mi][j][2 * half] * scale;
                float v1 = (cc + 1 > rr) ? -1e9f : acc[mi][j][2 * half + 1] * scale;
                *(float2*)&C[(size_t)rr * 2048 + cc] = make_float2(v0, v1);
            }
        }
}

__global__ __launch_bounds__(256, 1) void gemm_av() {
    extern __shared__ char smem[];
    const int z = blockIdx.z, b = z >> 3, h = z & 7;
    const int m0 = blockIdx.y * 256;       // t block
    const int d0 = blockIdx.x * 128;       // d block
    const int nc = (blockIdx.y + 1) * 8;   // causal K limit (chunks of 32)
    const size_t pbase = (size_t)z * TT * TT + (size_t)m0 * 2048;
    const size_t vbase = ((size_t)z * 512 + d0) * 2048;

    float acc[4][8][4];
    gemm_core3(g_ph + pbase, g_pl + pbase, 2048,
               g_vth + vbase, g_vtl + vbase, 2048,
               nc, smem, acc);
    EPI_IDX();
#pragma unroll
    for (int mi = 0; mi < 4; mi++)
#pragma unroll
        for (int j = 0; j < 8; j++) {
            const int cc = d0 + wn + j * 8 + ec;
#pragma unroll
            for (int half = 0; half < 2; half++) {
                const int rr = m0 + wm + mi * 16 + er + half * 8;
                const size_t o = (size_t)(b * TT + rr) * 4096 + h * 512 + cc;
                const float v0 = acc[mi][j][2 * half], v1 = acc[mi][j][2 * half + 1];
                __half l0, l1;
                const __half2 hi2 = split_hi2(v0, v1, l0, l1);
                *(__half2*)&g_oh[o] = hi2;
                *(__half2*)&g_ol[o] = __halves2half2(l0, l1);
            }
        }
}

__global__ __launch_bounds__(256, 1) void gemm_oproj(float* __restrict__ out) {
    extern __shared__ char smem[];
    const int m0 = blockIdx.y * 256, n0 = blockIdx.x * 128;
    float acc[4][8][4];
    gemm_core3(g_oh + (size_t)m0 * 4096, g_ol + (size_t)m0 * 4096, 4096,
               g_woh + (size_t)n0 * 4096, g_wol + (size_t)n0 * 4096, 4096,
               128, smem, acc);
    EPI_IDX();
#pragma unroll
    for (int mi = 0; mi < 4; mi++)
#pragma unroll
        for (int j = 0; j < 8; j++) {
            const int rr = m0 + wm + mi * 16 + er;
            const int cc = n0 + wn + j * 8 + ec;
            *(float2*)&out[(size_t)rr * 1024 + cc] = make_float2(acc[mi][j][0], acc[mi][j][1]);
            *(float2*)&out[(size_t)(rr + 8) * 1024 + cc] = make_float2(acc[mi][j][2], acc[mi][j][3]);
        }
}

// ---------------------------------------------------------------------------
// Conversions
// ---------------------------------------------------------------------------
__global__ __launch_bounds__(256) void conv_split(const float* __restrict__ s,
                                                  __half* __restrict__ h,
                                                  __half* __restrict__ l, int n) {
    const int i = (blockIdx.x * 256 + threadIdx.x) * 4;
    if (i >= n) return;
    float4 v = *(const float4*)(s + i);
    __half l0, l1, l2, l3;
    const __half2 h01 = split_hi2(v.x, v.y, l0, l1);
    const __half2 h23 = split_hi2(v.z, v.w, l2, l3);
    *(__half2*)(h + i)     = h01;
    *(__half2*)(h + i + 2) = h23;
    *(__half2*)(l + i)     = __halves2half2(l0, l1);
    *(__half2*)(l + i + 2) = __halves2half2(l2, l3);
}

__global__ __launch_bounds__(256) void conv_hi(const float* __restrict__ s,
                                               __half* __restrict__ h, int n) {
    const int i = (blockIdx.x * 256 + threadIdx.x) * 4;
    if (i >= n) return;
    float4 v = *(const float4*)(s + i);
    *(__half2*)(h + i)     = __halves2half2(__float2half_rn(v.x), __float2half_rn(v.y));
    *(__half2*)(h + i + 2) = __halves2half2(__float2half_rn(v.z), __float2half_rn(v.w));
}

// ---------------------------------------------------------------------------
// RoPE + split:  reads g_q/g_k fp32, writes qh/ql/kh/kl fp16.
// ---------------------------------------------------------------------------
__global__ __launch_bounds__(256) void rope_conv() {
    const size_t gid = (size_t)blockIdx.x * 256 + threadIdx.x;
    const size_t half = 8388608ull;
    const bool isK = gid >= half;
    const size_t id = gid & (half - 1);
    const int row = (int)(id >> 11);
    const int p = (int)(id & 2047);
    const int h = p >> 8;
    const int i = p & 255;
    const int t = row & (TT - 1);

    const float expo = (float)(2 * i) * (1.0f / 512.0f);
    const float inv_f = 1.0f / powf(10000.0f, expo);
    const float ang = (float)t * inv_f;
    float sn, cs;
    sincosf(ang, &sn, &cs);

    const size_t idx = (size_t)row * 4096 + h * 512 + 2 * i;
    const float* src = isK ? g_k : g_q;
    __half* dh = isK ? g_kh : g_qh;
    __half* dl = isK ? g_kl : g_ql;
    const float x1 = src[idx], x2 = src[idx + 1];
    const float r1 = x1 * cs - x2 * sn;
    const float r2 = x1 * sn + x2 * cs;
    __half l1, l2;
    const __half2 hi2 = split_hi2(r1, r2, l1, l2);
    *(__half2*)(dh + idx) = hi2;
    *(__half2*)(dl + idx) = __halves2half2(l1, l2);
}

// ---------------------------------------------------------------------------
// V transpose + split: g_v[(b,t),(h,d)] -> vt[(b,h), d, s] fp16 hi/lo
// ---------------------------------------------------------------------------
__global__ __launch_bounds__(256) void v_trans() {
    __shared__ float tile[32][33];
    const int z = blockIdx.z, b = z >> 3, h = z & 7;
    const int s0 = blockIdx.x * 32, d0 = blockIdx.y * 32;
    const int tx = threadIdx.x, ty = threadIdx.y;
#pragma unroll
    for (int i = 0; i < 4; i++) {
        const int s = s0 + ty + i * 8;
        tile[ty + i * 8][tx] = g_v[(size_t)(b * TT + s) * 4096 + h * 512 + d0 + tx];
    }
    __syncthreads();
#pragma unroll
    for (int i = 0; i < 4; i++) {
        const int d = d0 + ty + i * 8;
        const float f = tile[tx][ty + i * 8];
        const __half hi = __float2half_rn(f);
        const __half lo = __float2half_rn(f - __half2float(hi));
        const size_t o = ((size_t)z * 512 + d) * 2048 + s0 + tx;
        g_vth[o] = hi;
        g_vtl[o] = lo;
    }
}

// ---------------------------------------------------------------------------
// Softmax: fp32 scores in, fp16 hi/lo probs out.
// Zero-fills only to the next 256 boundary (AV never reads past it).
// ---------------------------------------------------------------------------
__global__ __launch_bounds__(256) void softmax2() {
    const int rI = blockIdx.x;
    const int t = rI & (TT - 1);
    float* row = g_s + (size_t)rI * TT;
    __half* ph = g_ph + (size_t)rI * TT;
    __half* pl = g_pl + (size_t)rI * TT;
    const int len = t + 1;
    const int fill_end = ((t >> 8) + 1) << 8;
    const int tid = threadIdx.x;
    __shared__ float red[256];

    float m = -1e30f;
    for (int s = tid; s < len; s += 256) m = fmaxf(m, row[s]);
    red[tid] = m;
    __syncthreads();
#pragma unroll
    for (int off = 128; off > 0; off >>= 1) {
        if (tid < off) red[tid] = fmaxf(red[tid], red[tid + off]);
        __syncthreads();
    }
    m = red[0];
    __syncthreads();

    float sum = 0.f;
    for (int s = tid; s < len; s += 256) {
        const float e = expf(row[s] - m);
        row[s] = e;
        sum += e;
    }
    red[tid] = sum;
    __syncthreads();
#pragma unroll
    for (int off = 128; off > 0; off >>= 1) {
        if (tid < off) red[tid] += red[tid + off];
        __syncthreads();
    }
    const float inv = 1.0f / red[0];

    for (int s = tid; s < len; s += 256) {
        const float pv = row[s] * inv;
        const __half hi = __float2half_rn(pv);
        ph[s] = hi;
        pl[s] = __float2half_rn(pv - __half2float(hi));
    }
    const __half z0 = __float2half_rn(0.f);
    for (int s = len + tid; s < fill_end; s += 256) { ph[s] = z0; pl[s] = z0; }
}

// ---------------------------------------------------------------------------
// Host orchestration
// ---------------------------------------------------------------------------
extern "C" void kernel_launch(void* const* d_in, const int* in_sizes, int n_in,
                              void* d_out, int out_size)
{
    const float* x  = (const float*)d_in[0];
    const float* wq = (const float*)d_in[1];
    const float* wk = (const float*)d_in[2];
    const float* wv = (const float*)d_in[3];
    const float* wo = (const float*)d_in[4];
    float* out = (float*)d_out;

    cudaFuncSetAttribute(gemm_qkv,    cudaFuncAttributeMaxDynamicSharedMemorySize, SMEM2_BYTES);
    cudaFuncSetAttribute(gemm_scores, cudaFuncAttributeMaxDynamicSharedMemorySize, SMEM3_BYTES);
    cudaFuncSetAttribute(gemm_av,     cudaFuncAttributeMaxDynamicSharedMemorySize, SMEM3_BYTES);
    cudaFuncSetAttribute(gemm_oproj,  cudaFuncAttributeMaxDynamicSharedMemorySize, SMEM3_BYTES);

    __half *xh, *wqh, *wql, *wkh, *wkl, *wvh, *wvl, *woh, *wol;
    cudaGetSymbolAddress((void**)&xh, g_xh);
    cudaGetSymbolAddress((void**)&wqh, g_wqh); cudaGetSymbolAddress((void**)&wql, g_wql);
    cudaGetSymbolAddress((void**)&wkh, g_wkh); cudaGetSymbolAddress((void**)&wkl, g_wkl);
    cudaGetSymbolAddress((void**)&wvh, g_wvh); cudaGetSymbolAddress((void**)&wvl, g_wvl);
    cudaGetSymbolAddress((void**)&woh, g_woh); cudaGetSymbolAddress((void**)&wol, g_wol);

    const int n4m = 4096 * 1024;
    conv_hi<<<n4m / 1024, 256>>>(x, xh, n4m);
    conv_split<<<n4m / 1024, 256>>>(wq, wqh, wql, n4m);
    conv_split<<<n4m / 1024, 256>>>(wk, wkh, wkl, n4m);
    conv_split<<<n4m / 1024, 256>>>(wv, wvh, wvl, n4m);
    conv_split<<<n4m / 1024, 256>>>(wo, woh, wol, n4m);

    gemm_qkv<<<dim3(32, 16, 3), 256, SMEM2_BYTES>>>();
    rope_conv<<<65536, 256>>>();
    v_trans<<<dim3(64, 16, 16), dim3(32, 8)>>>();
    gemm_scores<<<dim3(16, 8, 16), 256, SMEM3_BYTES>>>();
    softmax2<<<32768, 256>>>();
    gemm_av<<<dim3(4, 8, 16), 256, SMEM3_BYTES>>>();
    gemm_oproj<<<dim3(8, 16), 256, SMEM3_BYTES>>>(out);
}